// round 11
// baseline (speedup 1.0000x reference)
#include <cuda_runtime.h>
#include <cuda_bf16.h>
#include <cuda_fp16.h>
#include <math.h>

// ---------------- problem constants ----------------
#define NB   2
#define NCH  128
#define NH   128
#define NW   128
#define NE   6
#define ND   6
#define NHF  512
#define NHW  (NH*NW)        // 16384
#define NTOK (NB*NH*NW)     // 32768
#define NOUT (NTOK*NCH)
#define GBLK 128            // gate blocks (256 tokens each)
#define LCAP (2*NTOK)       // per-expert list capacity

// ---------------- scratch ----------------
__device__ float g_xf[NTOK * NCH];
__device__ float g_res[NTOK * 2 * NCH];
__device__ int   g_list[NE * LCAP];
__device__ float g_gate[NE * LCAP];
__device__ int   g_cnt[NE];
__device__ float g_partW[GBLK * NE];
__device__ float g_partC[GBLK * NE];
__device__ unsigned g_done;

// fp16 weights, B layout [n][k]
__device__ __align__(16) __half g_w1t[NE * NHF * NCH];
__device__ __align__(16) __half g_w2t[NE * NHF * NCH];

__device__ __forceinline__ float gelu_exact(float z) {
    return 0.5f * z * (1.0f + erff(z * 0.7071067811865475f));
}
__device__ __forceinline__ unsigned pack2h(float a0, float a1) {
    __half2 h = __floats2half2_rn(a0, a1);
    return *(unsigned*)&h;
}
__device__ __forceinline__ void mma16816h(float* c, const unsigned* a, const unsigned* b) {
    asm volatile("mma.sync.aligned.m16n8k16.row.col.f32.f16.f16.f32 "
                 "{%0,%1,%2,%3}, {%4,%5,%6,%7}, {%8,%9}, {%0,%1,%2,%3};"
                 : "+f"(c[0]), "+f"(c[1]), "+f"(c[2]), "+f"(c[3])
                 : "r"(a[0]), "r"(a[1]), "r"(a[2]), "r"(a[3]),
                   "r"(b[0]), "r"(b[1]));
}
__device__ __forceinline__ void ldm_x4(unsigned* r, unsigned addr) {
    asm volatile("ldmatrix.sync.aligned.m8n8.x4.shared.b16 {%0,%1,%2,%3}, [%4];"
                 : "=r"(r[0]), "=r"(r[1]), "=r"(r[2]), "=r"(r[3]) : "r"(addr));
}
__device__ __forceinline__ unsigned smem_u32(const void* p) {
    unsigned a;
    asm("{ .reg .u64 t; cvta.to.shared.u64 t, %1; cvt.u32.u64 %0, t; }" : "=r"(a) : "l"(p));
    return a;
}
#define CP16(dst, src) \
    asm volatile("cp.async.cg.shared.global [%0], [%1], 16;" :: "r"(dst), "l"(src))
#define CP_COMMIT() asm volatile("cp.async.commit_group;" ::: "memory")
#define CP_WAIT(n)  asm volatile("cp.async.wait_group %0;" :: "n"(n) : "memory")

// ---------------- kernel 1: zero counters only ----------------
__global__ void k_init() {
    int t = threadIdx.x;
    if (t < NE) g_cnt[t] = 0;
    if (t == 31) g_done = 0;
}

// ---------------- kernel 2: gating (coalesced from x, in-block bias) --------
__global__ void __launch_bounds__(256)
k_gate(const float* __restrict__ x, const float* __restrict__ prompt,
       const float* __restrict__ de_cls, const float* __restrict__ w_g,
       const float* __restrict__ gboost, const float* __restrict__ degra_w,
       const float* __restrict__ degra_b,
       float* __restrict__ out, int out_size) {
    __shared__ float wg_s[NCH * NE];
    __shared__ float bias_s[NE];
    __shared__ float wsum[8][NE];
    __shared__ int   wcnt[8][NE];
    __shared__ unsigned is_last_s;
    int tid = threadIdx.x;
    int warp = tid >> 5, lane = tid & 31;
    int n = blockIdx.x * 256 + tid;
    int b = n >> 14;                  // whole block shares one b (16384 % 256 == 0)

    for (int i = tid; i < NCH * NE; i += 256) wg_s[i] = w_g[i];

    if (warp < NE) {
        int e = warp;
        float s1 = 0.f;
#pragma unroll
        for (int q = 0; q < 4; q++) {
            int c = lane + q * 32;
            s1 += prompt[b * NCH + c] * w_g[(NCH + c) * NE + e];
        }
        float s2 = (lane < ND) ? de_cls[b * ND + lane] * degra_w[lane * NE + e] : 0.f;
        for (int off = 16; off; off >>= 1) {
            s1 += __shfl_down_sync(0xffffffffu, s1, off);
            s2 += __shfl_down_sync(0xffffffffu, s2, off);
        }
        if (lane == 0) bias_s[e] = s1 + gboost[0] * (s2 + degra_b[e]);
    }
    __syncthreads();

    int hw = n & (NHW - 1);
    float acc[NE];
#pragma unroll
    for (int e = 0; e < NE; e++) acc[e] = bias_s[e];
    const float* xb = x + (size_t)b * NCH * NHW + hw;
#pragma unroll 4
    for (int c = 0; c < NCH; c++) {
        float xv = xb[(size_t)c * NHW];
#pragma unroll
        for (int e = 0; e < NE; e++) acc[e] += xv * wg_s[c * NE + e];
    }
    int i0 = 0; float v0 = acc[0];
#pragma unroll
    for (int e = 1; e < NE; e++) if (acc[e] > v0) { v0 = acc[e]; i0 = e; }
    int i1 = (i0 == 0) ? 1 : 0; float v1 = acc[i1];
#pragma unroll
    for (int e = 0; e < NE; e++)
        if (e != i0 && acc[e] > v1) { v1 = acc[e]; i1 = e; }
    float g0 = 1.f / (1.f + expf(v1 - v0));
    float g1 = 1.f - g0;

    int p0 = atomicAdd(&g_cnt[i0], 1);
    g_list[i0 * LCAP + p0] = n * 2 + 0;
    g_gate[i0 * LCAP + p0] = g0;
    int p1 = atomicAdd(&g_cnt[i1], 1);
    g_list[i1 * LCAP + p1] = n * 2 + 1;
    g_gate[i1 * LCAP + p1] = g1;

#pragma unroll
    for (int e = 0; e < NE; e++) {
        float gv = (i0 == e ? g0 : 0.f) + (i1 == e ? g1 : 0.f);
        int   cv = (i0 == e) + (i1 == e);
        for (int off = 16; off; off >>= 1) {
            gv += __shfl_down_sync(0xffffffffu, gv, off);
            cv += __shfl_down_sync(0xffffffffu, cv, off);
        }
        if (lane == 0) { wsum[warp][e] = gv; wcnt[warp][e] = cv; }
    }
    __syncthreads();
    if (tid < NE) {
        float s = 0.f; int c = 0;
#pragma unroll
        for (int w = 0; w < 8; w++) { s += wsum[w][tid]; c += wcnt[w][tid]; }
        g_partW[blockIdx.x * NE + tid] = s;
        g_partC[blockIdx.x * NE + tid] = (float)c;
    }
    __threadfence();
    __syncthreads();
    if (tid == 0) is_last_s = (atomicAdd(&g_done, 1u) == GBLK - 1);
    __syncthreads();
    if (is_last_s) {
        if (warp < NE) {
            float sW = g_partW[lane * NE + warp] + g_partW[(lane + 32) * NE + warp]
                     + g_partW[(lane + 64) * NE + warp] + g_partW[(lane + 96) * NE + warp];
            float sC = g_partC[lane * NE + warp] + g_partC[(lane + 32) * NE + warp]
                     + g_partC[(lane + 64) * NE + warp] + g_partC[(lane + 96) * NE + warp];
            for (int off = 16; off; off >>= 1) {
                sW += __shfl_down_sync(0xffffffffu, sW, off);
                sC += __shfl_down_sync(0xffffffffu, sC, off);
            }
            if (lane == 0) { wsum[0][warp] = sW; wsum[1][warp] = sC; }
        }
        __syncthreads();
        if (tid == 0 && out_size > NOUT) {
            float mW = 0.f, mC = 0.f;
            for (int e = 0; e < NE; e++) { mW += wsum[0][e]; mC += wsum[1][e]; }
            mW /= NE; mC /= NE;
            float vW = 0.f, vC = 0.f;
            for (int e = 0; e < NE; e++) {
                vW += (wsum[0][e] - mW) * (wsum[0][e] - mW);
                vC += (wsum[1][e] - mC) * (wsum[1][e] - mC);
            }
            vW /= (NE - 1); vC /= (NE - 1);
            out[NOUT] = vW / (mW * mW + 1e-10f) + vC / (mC * mC + 1e-10f);
        }
    }
}

// ---------------- kernel 3: fused transpose + weight prep --------------------
#define TPBLK 4096
#define W1ELEM (NE * NHF * NCH)
__global__ void __launch_bounds__(256)
k_tp(const float* __restrict__ x,
     const float* __restrict__ fc1w, const float* __restrict__ fc2w) {
    __shared__ float tile[32][33];
    int bid = blockIdx.x;
    int tid = threadIdx.x;
    if (bid < TPBLK) {
        int cx = bid & 3, wy = (bid >> 2) & 3, bh = bid >> 4;
        int b = bh / NH, h = bh % NH;
        int c0 = cx * 32, w0 = wy * 32;
        int tx = tid & 31, ty = tid >> 5;
        for (int i = ty; i < 32; i += 8)
            tile[i][tx] = x[(((size_t)b * NCH + c0 + i) * NH + h) * NW + w0 + tx];
        __syncthreads();
        for (int i = ty; i < 32; i += 8)
            g_xf[((size_t)(b * NHW + h * NW + w0 + i)) * NCH + c0 + tx] = tile[tx][i];
    } else {
        int idx = (bid - TPBLK) * 256 + tid;
        if (idx < W1ELEM) {
            int e = idx >> 16, rem = idx & 65535;
            int n = rem >> 7, k = rem & 127;
            g_w1t[idx] = __float2half_rn(fc1w[((size_t)e * NCH + k) * NHF + n]);
        } else {
            int j = idx - W1ELEM;
            if (j < W1ELEM) {
                int e = j >> 16, rem = j & 65535;
                int jc = rem >> 13, r2 = rem & 8191;
                int c = r2 >> 6, k = r2 & 63;
                g_w2t[j] = __float2half_rn(fc2w[((size_t)e * NHF + jc * 64 + k) * NCH + c]);
            }
        }
    }
}

// ---------------- kernel 4: fp16 mma MoE, register-fused H -------------------
// SMEM map (bytes):
#define S2_X     0                     // [128][136] half = 34816
#define S2_W1    34816                 // 2 buffers x [64][136] half = 2*17408
#define S2_W2    69632                 // 2 buffers x [128][72] half = 2*18432
#define S2_SLOT  106496
#define S2_GATE  107008
#define S2_BYTES 107520

__global__ void __launch_bounds__(256, 2)
k_moe(const float* __restrict__ fc1b, const float* __restrict__ fc2b) {
    int e    = blockIdx.x >> 9;
    int tile = blockIdx.x & 511;
    int cnt  = g_cnt[e];
    int row0 = tile << 7;
    if (row0 >= cnt) return;

    extern __shared__ char sm[];
    unsigned sb = smem_u32(sm);
    int*   slot_s = (int*)(sm + S2_SLOT);
    float* gate_s = (float*)(sm + S2_GATE);

    int tid = threadIdx.x;
    int wid = tid >> 5, lt = tid & 31;
    int qr = lt >> 2, qc = lt & 3;
    int m0 = wid * 16;                 // each warp owns m16, full n
    int lrow = lt & 15;
    int lcol = (lt & 16) >> 1;         // 0 or 8 (halfs)

    const __half* w1g = g_w1t + (size_t)e * NHF * NCH;
    const __half* w2g = g_w2t + (size_t)e * NHF * NCH;

    // prologue: issue W1(0) + W2(0) into buffer 0 (one group)
    {
        unsigned d1 = sb + S2_W1, d2 = sb + S2_W2;
#pragma unroll
        for (int it = 0; it < 4; it++) {
            int u = tid + it * 256;              // 0..1023
            int n1 = u >> 4, k16 = u & 15;
            CP16(d1 + (unsigned)(n1 * 136 + k16 * 8) * 2, w1g + n1 * NCH + k16 * 8);
            int n2 = u >> 3, k8 = u & 7;
            CP16(d2 + (unsigned)(n2 * 72 + k8 * 8) * 2, w2g + n2 * 64 + k8 * 8);
        }
        CP_COMMIT();
    }

    if (tid < 128) {
        int r = row0 + tid;
        if (r < cnt) { slot_s[tid] = g_list[e * LCAP + r]; gate_s[tid] = g_gate[e * LCAP + r]; }
        else         { slot_s[tid] = -1; gate_s[tid] = 0.f; }
    }
    __syncthreads();

    // gather X -> fp16
#pragma unroll
    for (int it = 0; it < 8; it++) {
        int idx = tid + it * 256;
        int r = idx >> 4, c8 = idx & 15;
        float v[8];
        int s = slot_s[r];
        if (s >= 0) {
            const float4* src = (const float4*)(g_xf + (size_t)(s >> 1) * NCH + c8 * 8);
            float4 a = src[0], b = src[1];
            v[0]=a.x; v[1]=a.y; v[2]=a.z; v[3]=a.w; v[4]=b.x; v[5]=b.y; v[6]=b.z; v[7]=b.w;
        } else {
#pragma unroll
            for (int q = 0; q < 8; q++) v[q] = 0.f;
        }
        uint4 U;
        U.x = pack2h(v[0], v[1]);
        U.y = pack2h(v[2], v[3]);
        U.z = pack2h(v[4], v[5]);
        U.w = pack2h(v[6], v[7]);
        *(uint4*)((__half*)(sm + S2_X) + r * 136 + c8 * 8) = U;
    }

    float acc2[16][4];
#pragma unroll
    for (int j = 0; j < 16; j++)
#pragma unroll
        for (int q = 0; q < 4; q++) acc2[j][q] = 0.f;

    unsigned aX = sb + S2_X + (unsigned)((m0 + lrow) * 136 + lcol) * 2;

    for (int jc = 0; jc < 8; jc++) {
        int cur = jc & 1;
        CP_WAIT(0);              // W1(jc)+W2(jc) arrived
        __syncthreads();         // visible to all warps; prev buffers fully consumed

        // issue W1(jc+1)+W2(jc+1) into other buffers (overlaps compute)
        if (jc < 7) {
            unsigned d1 = sb + S2_W1 + (1 - cur) * 17408;
            unsigned d2 = sb + S2_W2 + (1 - cur) * 18432;
            const __half* s1 = w1g + (jc + 1) * 64 * NCH;
            const __half* s2 = w2g + (jc + 1) * 8192;
#pragma unroll
            for (int it = 0; it < 4; it++) {
                int u = tid + it * 256;
                int n1 = u >> 4, k16 = u & 15;
                CP16(d1 + (unsigned)(n1 * 136 + k16 * 8) * 2, s1 + n1 * NCH + k16 * 8);
                int n2 = u >> 3, k8 = u & 7;
                CP16(d2 + (unsigned)(n2 * 72 + k8 * 8) * 2, s2 + n2 * 64 + k8 * 8);
            }
            CP_COMMIT();
        }

        unsigned bW1base = sb + S2_W1 + cur * 17408 + (unsigned)(lrow * 136 + lcol) * 2;
        unsigned bW2base = sb + S2_W2 + cur * 18432 + (unsigned)(lrow * 72 + lcol) * 2;

        // GEMM1 (m16 x n64) in two n32 halves; gelu packs straight into
        // GEMM2 A-fragments (C-fragment layout == A-fragment layout).
        unsigned afrag[4][4];
#pragma unroll
        for (int h = 0; h < 2; h++) {
            float acc1[4][4];
#pragma unroll
            for (int j = 0; j < 4; j++)
#pragma unroll
                for (int q = 0; q < 4; q++) acc1[j][q] = 0.f;

#pragma unroll
            for (int kt = 0; kt < 8; kt++) {
                unsigned a[4];
                ldm_x4(a, aX + kt * 32);
#pragma unroll
                for (int j2 = 0; j2 < 2; j2++) {
                    unsigned r[4];
                    ldm_x4(r, bW1base + (unsigned)((h * 2 + j2) * 16 * 136) * 2 + kt * 32);
                    unsigned b0[2] = { r[0], r[2] };
                    unsigned b1[2] = { r[1], r[3] };
                    mma16816h(acc1[2 * j2],     a, b0);
                    mma16816h(acc1[2 * j2 + 1], a, b1);
                }
            }
            // bias + gelu -> A-fragments for GEMM2 (k-tiles 2h, 2h+1)
#pragma unroll
            for (int j = 0; j < 4; j++) {
                int jg = h * 4 + j;                        // global n8 tile
                int n = jg * 8 + qc * 2;
                float2 b1v = *(const float2*)(fc1b + e * NHF + jc * 64 + n);
                unsigned lohi0 = pack2h(gelu_exact(acc1[j][0] + b1v.x),
                                        gelu_exact(acc1[j][1] + b1v.y));
                unsigned lohi1 = pack2h(gelu_exact(acc1[j][2] + b1v.x),
                                        gelu_exact(acc1[j][3] + b1v.y));
                int kt2 = jg >> 1, sl = (jg & 1) * 2;
                afrag[kt2][sl]     = lohi0;
                afrag[kt2][sl + 1] = lohi1;
            }
        }

        // GEMM2 (m16 x n128), A in registers, B from smem
#pragma unroll
        for (int kt2 = 0; kt2 < 4; kt2++) {
#pragma unroll
            for (int j2 = 0; j2 < 8; j2++) {
                unsigned r[4];
                ldm_x4(r, bW2base + (unsigned)(j2 * 16 * 72) * 2 + kt2 * 32);
                unsigned b0[2] = { r[0], r[2] };
                unsigned b1[2] = { r[1], r[3] };
                mma16816h(acc2[2 * j2],     afrag[kt2], b0);
                mma16816h(acc2[2 * j2 + 1], afrag[kt2], b1);
            }
        }
    }

    // epilogue: gate * exp(out + b2) -> g_res
    int mAr = m0 + qr, mBr = mAr + 8;
    int sA = slot_s[mAr], sB = slot_s[mBr];
    float gA = gate_s[mAr], gB = gate_s[mBr];
#pragma unroll
    for (int j = 0; j < 16; j++) {
        int c = j * 8 + qc * 2;
        float2 b2 = *(const float2*)(fc2b + e * NCH + c);
        if (sA >= 0) {
            float2 o;
            o.x = gA * __expf(acc2[j][0] + b2.x);
            o.y = gA * __expf(acc2[j][1] + b2.y);
            *(float2*)(g_res + (size_t)sA * NCH + c) = o;
        }
        if (sB >= 0) {
            float2 o;
            o.x = gB * __expf(acc2[j][2] + b2.x);
            o.y = gB * __expf(acc2[j][3] + b2.y);
            *(float2*)(g_res + (size_t)sB * NCH + c) = o;
        }
    }
}

// ---------------- kernel 5: combine + log + transpose back ----------------
__global__ void k_out(float* __restrict__ out) {
    __shared__ float tile[32][33];
    int bh = blockIdx.z;
    int b = bh / NH, h = bh % NH;
    int c0 = blockIdx.x * 32, w0 = blockIdx.y * 32;
    int tx = threadIdx.x, ty = threadIdx.y;
    for (int i = ty; i < 32; i += 8) {
        size_t base = (size_t)(b * NHW + h * NW + w0 + i) * 2 * NCH;
        float v = g_res[base + c0 + tx] + g_res[base + NCH + c0 + tx];
        if (v == 0.f) v = 2.2204460492503131e-16f;
        tile[i][tx] = logf(v);
    }
    __syncthreads();
    for (int i = ty; i < 32; i += 8)
        out[(((size_t)b * NCH + c0 + i) * NH + h) * NW + w0 + tx] = tile[tx][i];
}

// ---------------- launch ----------------
extern "C" void kernel_launch(void* const* d_in, const int* in_sizes, int n_in,
                              void* d_out, int out_size) {
    (void)in_sizes; (void)n_in;
    const float* x       = (const float*)d_in[0];
    const float* prompt  = (const float*)d_in[1];
    const float* de_cls  = (const float*)d_in[2];
    const float* w_g     = (const float*)d_in[3];
    const float* gboost  = (const float*)d_in[4];
    const float* degra_w = (const float*)d_in[5];
    const float* degra_b = (const float*)d_in[6];
    const float* fc1w    = (const float*)d_in[7];
    const float* fc1b    = (const float*)d_in[8];
    const float* fc2w    = (const float*)d_in[9];
    const float* fc2b    = (const float*)d_in[10];
    float* out = (float*)d_out;

    k_init<<<1, 32>>>();
    k_gate<<<GBLK, 256>>>(x, prompt, de_cls, w_g, gboost, degra_w, degra_b,
                          out, out_size);
    k_tp<<<TPBLK + 3072, 256>>>(x, fc1w, fc2w);

    cudaFuncSetAttribute(k_moe, cudaFuncAttributeMaxDynamicSharedMemorySize, S2_BYTES);
    k_moe<<<NE * 512, 256, S2_BYTES>>>(fc1b, fc2b);

    k_out<<<dim3(NCH / 32, NW / 32, NB * NH), dim3(32, 8)>>>(out);
}

// round 12
// speedup vs baseline: 1.2054x; 1.2054x over previous
#include <cuda_runtime.h>
#include <cuda_bf16.h>
#include <cuda_fp16.h>
#include <math.h>

// ---------------- problem constants ----------------
#define NB   2
#define NCH  128
#define NH   128
#define NW   128
#define NE   6
#define ND   6
#define NHF  512
#define NHW  (NH*NW)        // 16384
#define NTOK (NB*NH*NW)     // 32768
#define NOUT (NTOK*NCH)
#define GBLK 128            // gate blocks (256 tokens each)
#define LCAP (2*NTOK)       // per-expert list capacity

// ---------------- scratch ----------------
__device__ float g_xf[NTOK * NCH];
__device__ float g_res[NTOK * 2 * NCH];
__device__ int   g_list[NE * LCAP];
__device__ float g_gate[NE * LCAP];
__device__ int   g_cnt[NE];
__device__ float g_partW[GBLK * NE];
__device__ float g_partC[GBLK * NE];
__device__ unsigned g_done;

// fp16 weights, B layout [n][k]
__device__ __align__(16) __half g_w1t[NE * NHF * NCH];
__device__ __align__(16) __half g_w2t[NE * NHF * NCH];

// fast gelu: tanh approximation, MUFU tanh (H is fp16-quantized anyway;
// approximation error ~3e-5 abs at |z|<1.5, far below W-quant error floor)
__device__ __forceinline__ float gelu_fast(float z) {
    float u = 0.7978845608028654f * z * (1.0f + 0.044715f * z * z);
    float t;
    asm("tanh.approx.f32 %0, %1;" : "=f"(t) : "f"(u));
    return 0.5f * z * (1.0f + t);
}
__device__ __forceinline__ unsigned pack2h(float a0, float a1) {
    __half2 h = __floats2half2_rn(a0, a1);
    return *(unsigned*)&h;
}
__device__ __forceinline__ void mma16816h(float* c, const unsigned* a, const unsigned* b) {
    asm volatile("mma.sync.aligned.m16n8k16.row.col.f32.f16.f16.f32 "
                 "{%0,%1,%2,%3}, {%4,%5,%6,%7}, {%8,%9}, {%0,%1,%2,%3};"
                 : "+f"(c[0]), "+f"(c[1]), "+f"(c[2]), "+f"(c[3])
                 : "r"(a[0]), "r"(a[1]), "r"(a[2]), "r"(a[3]),
                   "r"(b[0]), "r"(b[1]));
}
__device__ __forceinline__ void ldm_x4(unsigned* r, unsigned addr) {
    asm volatile("ldmatrix.sync.aligned.m8n8.x4.shared.b16 {%0,%1,%2,%3}, [%4];"
                 : "=r"(r[0]), "=r"(r[1]), "=r"(r[2]), "=r"(r[3]) : "r"(addr));
}
__device__ __forceinline__ unsigned smem_u32(const void* p) {
    unsigned a;
    asm("{ .reg .u64 t; cvta.to.shared.u64 t, %1; cvt.u32.u64 %0, t; }" : "=r"(a) : "l"(p));
    return a;
}
#define CP16(dst, src) \
    asm volatile("cp.async.cg.shared.global [%0], [%1], 16;" :: "r"(dst), "l"(src))
#define CP_COMMIT() asm volatile("cp.async.commit_group;" ::: "memory")
#define CP_WAIT(n)  asm volatile("cp.async.wait_group %0;" :: "n"(n) : "memory")

// ---------------- kernel 1: zero counters only ----------------
__global__ void k_init() {
    int t = threadIdx.x;
    if (t < NE) g_cnt[t] = 0;
    if (t == 31) g_done = 0;
}

// ---------------- kernel 2: gating (coalesced from x, in-block bias) --------
__global__ void __launch_bounds__(256)
k_gate(const float* __restrict__ x, const float* __restrict__ prompt,
       const float* __restrict__ de_cls, const float* __restrict__ w_g,
       const float* __restrict__ gboost, const float* __restrict__ degra_w,
       const float* __restrict__ degra_b,
       float* __restrict__ out, int out_size) {
    __shared__ float wg_s[NCH * NE];
    __shared__ float bias_s[NE];
    __shared__ float wsum[8][NE];
    __shared__ int   wcnt[8][NE];
    __shared__ unsigned is_last_s;
    int tid = threadIdx.x;
    int warp = tid >> 5, lane = tid & 31;
    int n = blockIdx.x * 256 + tid;
    int b = n >> 14;                  // whole block shares one b (16384 % 256 == 0)

    for (int i = tid; i < NCH * NE; i += 256) wg_s[i] = w_g[i];

    if (warp < NE) {
        int e = warp;
        float s1 = 0.f;
#pragma unroll
        for (int q = 0; q < 4; q++) {
            int c = lane + q * 32;
            s1 += prompt[b * NCH + c] * w_g[(NCH + c) * NE + e];
        }
        float s2 = (lane < ND) ? de_cls[b * ND + lane] * degra_w[lane * NE + e] : 0.f;
        for (int off = 16; off; off >>= 1) {
            s1 += __shfl_down_sync(0xffffffffu, s1, off);
            s2 += __shfl_down_sync(0xffffffffu, s2, off);
        }
        if (lane == 0) bias_s[e] = s1 + gboost[0] * (s2 + degra_b[e]);
    }
    __syncthreads();

    int hw = n & (NHW - 1);
    float acc[NE];
#pragma unroll
    for (int e = 0; e < NE; e++) acc[e] = bias_s[e];
    const float* xb = x + (size_t)b * NCH * NHW + hw;
#pragma unroll 4
    for (int c = 0; c < NCH; c++) {
        float xv = xb[(size_t)c * NHW];
#pragma unroll
        for (int e = 0; e < NE; e++) acc[e] += xv * wg_s[c * NE + e];
    }
    int i0 = 0; float v0 = acc[0];
#pragma unroll
    for (int e = 1; e < NE; e++) if (acc[e] > v0) { v0 = acc[e]; i0 = e; }
    int i1 = (i0 == 0) ? 1 : 0; float v1 = acc[i1];
#pragma unroll
    for (int e = 0; e < NE; e++)
        if (e != i0 && acc[e] > v1) { v1 = acc[e]; i1 = e; }
    float g0 = 1.f / (1.f + expf(v1 - v0));
    float g1 = 1.f - g0;

    int p0 = atomicAdd(&g_cnt[i0], 1);
    g_list[i0 * LCAP + p0] = n * 2 + 0;
    g_gate[i0 * LCAP + p0] = g0;
    int p1 = atomicAdd(&g_cnt[i1], 1);
    g_list[i1 * LCAP + p1] = n * 2 + 1;
    g_gate[i1 * LCAP + p1] = g1;

#pragma unroll
    for (int e = 0; e < NE; e++) {
        float gv = (i0 == e ? g0 : 0.f) + (i1 == e ? g1 : 0.f);
        int   cv = (i0 == e) + (i1 == e);
        for (int off = 16; off; off >>= 1) {
            gv += __shfl_down_sync(0xffffffffu, gv, off);
            cv += __shfl_down_sync(0xffffffffu, cv, off);
        }
        if (lane == 0) { wsum[warp][e] = gv; wcnt[warp][e] = cv; }
    }
    __syncthreads();
    if (tid < NE) {
        float s = 0.f; int c = 0;
#pragma unroll
        for (int w = 0; w < 8; w++) { s += wsum[w][tid]; c += wcnt[w][tid]; }
        g_partW[blockIdx.x * NE + tid] = s;
        g_partC[blockIdx.x * NE + tid] = (float)c;
    }
    __threadfence();
    __syncthreads();
    if (tid == 0) is_last_s = (atomicAdd(&g_done, 1u) == GBLK - 1);
    __syncthreads();
    if (is_last_s) {
        if (warp < NE) {
            float sW = g_partW[lane * NE + warp] + g_partW[(lane + 32) * NE + warp]
                     + g_partW[(lane + 64) * NE + warp] + g_partW[(lane + 96) * NE + warp];
            float sC = g_partC[lane * NE + warp] + g_partC[(lane + 32) * NE + warp]
                     + g_partC[(lane + 64) * NE + warp] + g_partC[(lane + 96) * NE + warp];
            for (int off = 16; off; off >>= 1) {
                sW += __shfl_down_sync(0xffffffffu, sW, off);
                sC += __shfl_down_sync(0xffffffffu, sC, off);
            }
            if (lane == 0) { wsum[0][warp] = sW; wsum[1][warp] = sC; }
        }
        __syncthreads();
        if (tid == 0 && out_size > NOUT) {
            float mW = 0.f, mC = 0.f;
            for (int e = 0; e < NE; e++) { mW += wsum[0][e]; mC += wsum[1][e]; }
            mW /= NE; mC /= NE;
            float vW = 0.f, vC = 0.f;
            for (int e = 0; e < NE; e++) {
                vW += (wsum[0][e] - mW) * (wsum[0][e] - mW);
                vC += (wsum[1][e] - mC) * (wsum[1][e] - mC);
            }
            vW /= (NE - 1); vC /= (NE - 1);
            out[NOUT] = vW / (mW * mW + 1e-10f) + vC / (mC * mC + 1e-10f);
        }
    }
}

// ---------------- kernel 3: fused transpose + weight prep --------------------
#define TPBLK 4096
#define W1ELEM (NE * NHF * NCH)
__global__ void __launch_bounds__(256)
k_tp(const float* __restrict__ x,
     const float* __restrict__ fc1w, const float* __restrict__ fc2w) {
    __shared__ float tile[32][33];
    int bid = blockIdx.x;
    int tid = threadIdx.x;
    if (bid < TPBLK) {
        int cx = bid & 3, wy = (bid >> 2) & 3, bh = bid >> 4;
        int b = bh / NH, h = bh % NH;
        int c0 = cx * 32, w0 = wy * 32;
        int tx = tid & 31, ty = tid >> 5;
        for (int i = ty; i < 32; i += 8)
            tile[i][tx] = x[(((size_t)b * NCH + c0 + i) * NH + h) * NW + w0 + tx];
        __syncthreads();
        for (int i = ty; i < 32; i += 8)
            g_xf[((size_t)(b * NHW + h * NW + w0 + i)) * NCH + c0 + tx] = tile[tx][i];
    } else {
        int idx = (bid - TPBLK) * 256 + tid;
        if (idx < W1ELEM) {
            int e = idx >> 16, rem = idx & 65535;
            int n = rem >> 7, k = rem & 127;
            g_w1t[idx] = __float2half_rn(fc1w[((size_t)e * NCH + k) * NHF + n]);
        } else {
            int j = idx - W1ELEM;
            if (j < W1ELEM) {
                int e = j >> 16, rem = j & 65535;
                int jc = rem >> 13, r2 = rem & 8191;
                int c = r2 >> 6, k = r2 & 63;
                g_w2t[j] = __float2half_rn(fc2w[((size_t)e * NHF + jc * 64 + k) * NCH + c]);
            }
        }
    }
}

// ---------------- kernel 4: fp16 mma MoE, m32 warp tiles, fast gelu ----------
// SMEM map (bytes):
#define S2_X     0                     // [128][136] half = 34816
#define S2_W1    34816                 // 2 buffers x [64][136] half = 2*17408
#define S2_W2    69632                 // [128][72] half = 18432
#define S2_H     88064                 // [128][72] half = 18432
#define S2_SLOT  106496
#define S2_GATE  107008
#define S2_BYTES 107520

__global__ void __launch_bounds__(256, 2)
k_moe(const float* __restrict__ fc1b, const float* __restrict__ fc2b) {
    int e    = blockIdx.x >> 9;
    int tile = blockIdx.x & 511;
    int cnt  = g_cnt[e];
    int row0 = tile << 7;
    if (row0 >= cnt) return;

    extern __shared__ char sm[];
    unsigned sb = smem_u32(sm);
    __half* Hs = (__half*)(sm + S2_H);
    int*   slot_s = (int*)(sm + S2_SLOT);
    float* gate_s = (float*)(sm + S2_GATE);

    int tid = threadIdx.x;
    int wid = tid >> 5, lt = tid & 31;
    int qr = lt >> 2, qc = lt & 3;
    int mb  = (wid & 3) * 32;          // warp m-block (32 rows)
    int nb1 = (wid >> 2) * 32;         // GEMM1 n-block (32 of 64)
    int nb2 = (wid >> 2) * 64;         // GEMM2 n-block (64 of 128)
    int lrow = lt & 15;
    int lcol = (lt & 16) >> 1;         // 0 or 8 (halfs)

    const __half* w1g = g_w1t + (size_t)e * NHF * NCH;
    const __half* w2g = g_w2t + (size_t)e * NHF * NCH;

    // prefetch W1 chunk 0 into buffer 0
    {
        unsigned d = sb + S2_W1;
#pragma unroll
        for (int it = 0; it < 4; it++) {
            int u = tid + it * 256;              // 0..1023
            int n1 = u >> 4, k16 = u & 15;
            CP16(d + (unsigned)(n1 * 136 + k16 * 8) * 2, w1g + n1 * NCH + k16 * 8);
        }
        CP_COMMIT();
    }

    if (tid < 128) {
        int r = row0 + tid;
        if (r < cnt) { slot_s[tid] = g_list[e * LCAP + r]; gate_s[tid] = g_gate[e * LCAP + r]; }
        else         { slot_s[tid] = -1; gate_s[tid] = 0.f; }
    }
    __syncthreads();

    // gather X -> fp16
#pragma unroll
    for (int it = 0; it < 8; it++) {
        int idx = tid + it * 256;
        int r = idx >> 4, c8 = idx & 15;
        float v[8];
        int s = slot_s[r];
        if (s >= 0) {
            const float4* src = (const float4*)(g_xf + (size_t)(s >> 1) * NCH + c8 * 8);
            float4 a = src[0], b = src[1];
            v[0]=a.x; v[1]=a.y; v[2]=a.z; v[3]=a.w; v[4]=b.x; v[5]=b.y; v[6]=b.z; v[7]=b.w;
        } else {
#pragma unroll
            for (int q = 0; q < 8; q++) v[q] = 0.f;
        }
        uint4 U;
        U.x = pack2h(v[0], v[1]);
        U.y = pack2h(v[2], v[3]);
        U.z = pack2h(v[4], v[5]);
        U.w = pack2h(v[6], v[7]);
        *(uint4*)((__half*)(sm + S2_X) + r * 136 + c8 * 8) = U;
    }

    float acc2[2][8][4];
#pragma unroll
    for (int i = 0; i < 2; i++)
#pragma unroll
        for (int j = 0; j < 8; j++)
#pragma unroll
            for (int q = 0; q < 4; q++) acc2[i][j][q] = 0.f;

    // per-lane ldmatrix base addresses (bytes)
    unsigned aX  = sb + S2_X  + (unsigned)((mb + lrow) * 136 + lcol) * 2;
    unsigned aH  = sb + S2_H  + (unsigned)((mb + lrow) * 72  + lcol) * 2;
    unsigned bW2 = sb + S2_W2 + (unsigned)((nb2 + lrow) * 72 + lcol) * 2;

    for (int jc = 0; jc < 8; jc++) {
        int cur = jc & 1;
        unsigned bW1 = sb + S2_W1 + cur * 17408 + (unsigned)((nb1 + lrow) * 136 + lcol) * 2;

        // issue W2(jc) async
        {
            unsigned d2 = sb + S2_W2;
            const __half* s2 = w2g + jc * 8192;
#pragma unroll
            for (int it = 0; it < 4; it++) {
                int u = tid + it * 256;
                int n2 = u >> 3, k8 = u & 7;
                CP16(d2 + (unsigned)(n2 * 72 + k8 * 8) * 2, s2 + n2 * 64 + k8 * 8);
            }
            CP_COMMIT();
        }
        CP_WAIT(1);              // W1(jc) arrived
        __syncthreads();

        // GEMM1: warp tile m32 x n32, A reused across both n16 groups
        float acc1[2][4][4];
#pragma unroll
        for (int i = 0; i < 2; i++)
#pragma unroll
            for (int j = 0; j < 4; j++)
#pragma unroll
                for (int q = 0; q < 4; q++) acc1[i][j][q] = 0.f;

#pragma unroll
        for (int kt = 0; kt < 8; kt++) {
            unsigned a0[4], a1[4];
            ldm_x4(a0, aX + kt * 32);
            ldm_x4(a1, aX + 16 * 136 * 2 + kt * 32);
#pragma unroll
            for (int j2 = 0; j2 < 2; j2++) {
                unsigned r[4];
                ldm_x4(r, bW1 + (unsigned)(j2 * 16 * 136) * 2 + kt * 32);
                unsigned b0[2] = { r[0], r[2] };
                unsigned b1[2] = { r[1], r[3] };
                mma16816h(acc1[0][2 * j2],     a0, b0);
                mma16816h(acc1[0][2 * j2 + 1], a0, b1);
                mma16816h(acc1[1][2 * j2],     a1, b0);
                mma16816h(acc1[1][2 * j2 + 1], a1, b1);
            }
        }
        // bias + fast gelu -> H (warp writes rows mb..mb+31, cols nb1..nb1+31)
#pragma unroll
        for (int i = 0; i < 2; i++)
#pragma unroll
            for (int j = 0; j < 4; j++) {
                int n = nb1 + j * 8 + qc * 2;
                float2 b1v = *(const float2*)(fc1b + e * NHF + jc * 64 + n);
                *(unsigned*)(Hs + (mb + i * 16 + qr) * 72 + n) =
                    pack2h(gelu_fast(acc1[i][j][0] + b1v.x),
                           gelu_fast(acc1[i][j][1] + b1v.y));
                *(unsigned*)(Hs + (mb + i * 16 + qr + 8) * 72 + n) =
                    pack2h(gelu_fast(acc1[i][j][2] + b1v.x),
                           gelu_fast(acc1[i][j][3] + b1v.y));
            }
        CP_WAIT(0);              // W2(jc) arrived
        __syncthreads();         // H visible + W2 visible

        // prefetch W1(jc+1) during GEMM2
        if (jc < 7) {
            unsigned d = sb + S2_W1 + (1 - cur) * 17408;
            const __half* s1 = w1g + (jc + 1) * 64 * NCH;
#pragma unroll
            for (int it = 0; it < 4; it++) {
                int u = tid + it * 256;
                int n1 = u >> 4, k16 = u & 15;
                CP16(d + (unsigned)(n1 * 136 + k16 * 8) * 2, s1 + n1 * NCH + k16 * 8);
            }
            CP_COMMIT();
        }

        // GEMM2: warp tile m32 x n64
#pragma unroll
        for (int kt = 0; kt < 4; kt++) {
            unsigned a0[4], a1[4];
            ldm_x4(a0, aH + kt * 32);
            ldm_x4(a1, aH + 16 * 72 * 2 + kt * 32);
#pragma unroll
            for (int j2 = 0; j2 < 4; j2++) {
                unsigned r[4];
                ldm_x4(r, bW2 + (unsigned)(j2 * 16 * 72) * 2 + kt * 32);
                unsigned b0[2] = { r[0], r[2] };
                unsigned b1[2] = { r[1], r[3] };
                mma16816h(acc2[0][2 * j2],     a0, b0);
                mma16816h(acc2[0][2 * j2 + 1], a0, b1);
                mma16816h(acc2[1][2 * j2],     a1, b0);
                mma16816h(acc2[1][2 * j2 + 1], a1, b1);
            }
        }
        __syncthreads();         // protect H + W2 for next chunk
    }

    // epilogue: gate * exp(out + b2) -> g_res
#pragma unroll
    for (int i = 0; i < 2; i++) {
        int mAr = mb + i * 16 + qr, mBr = mAr + 8;
        int sA = slot_s[mAr], sB = slot_s[mBr];
        float gA = gate_s[mAr], gB = gate_s[mBr];
#pragma unroll
        for (int j = 0; j < 8; j++) {
            int c = nb2 + j * 8 + qc * 2;
            float2 b2 = *(const float2*)(fc2b + e * NCH + c);
            if (sA >= 0) {
                float2 o;
                o.x = gA * __expf(acc2[i][j][0] + b2.x);
                o.y = gA * __expf(acc2[i][j][1] + b2.y);
                *(float2*)(g_res + (size_t)sA * NCH + c) = o;
            }
            if (sB >= 0) {
                float2 o;
                o.x = gB * __expf(acc2[i][j][2] + b2.x);
                o.y = gB * __expf(acc2[i][j][3] + b2.y);
                *(float2*)(g_res + (size_t)sB * NCH + c) = o;
            }
        }
    }
}

// ---------------- kernel 5: combine + log + transpose back ----------------
__global__ void k_out(float* __restrict__ out) {
    __shared__ float tile[32][33];
    int bh = blockIdx.z;
    int b = bh / NH, h = bh % NH;
    int c0 = blockIdx.x * 32, w0 = blockIdx.y * 32;
    int tx = threadIdx.x, ty = threadIdx.y;
    for (int i = ty; i < 32; i += 8) {
        size_t base = (size_t)(b * NHW + h * NW + w0 + i) * 2 * NCH;
        float v = g_res[base + c0 + tx] + g_res[base + NCH + c0 + tx];
        if (v == 0.f) v = 2.2204460492503131e-16f;
        tile[i][tx] = logf(v);
    }
    __syncthreads();
    for (int i = ty; i < 32; i += 8)
        out[(((size_t)b * NCH + c0 + i) * NH + h) * NW + w0 + tx] = tile[tx][i];
}

// ---------------- launch ----------------
extern "C" void kernel_launch(void* const* d_in, const int* in_sizes, int n_in,
                              void* d_out, int out_size) {
    (void)in_sizes; (void)n_in;
    const float* x       = (const float*)d_in[0];
    const float* prompt  = (const float*)d_in[1];
    const float* de_cls  = (const float*)d_in[2];
    const float* w_g     = (const float*)d_in[3];
    const float* gboost  = (const float*)d_in[4];
    const float* degra_w = (const float*)d_in[5];
    const float* degra_b = (const float*)d_in[6];
    const float* fc1w    = (const float*)d_in[7];
    const float* fc1b    = (const float*)d_in[8];
    const float* fc2w    = (const float*)d_in[9];
    const float* fc2b    = (const float*)d_in[10];
    float* out = (float*)d_out;

    k_init<<<1, 32>>>();
    k_gate<<<GBLK, 256>>>(x, prompt, de_cls, w_g, gboost, degra_w, degra_b,
                          out, out_size);
    k_tp<<<TPBLK + 3072, 256>>>(x, fc1w, fc2w);

    cudaFuncSetAttribute(k_moe, cudaFuncAttributeMaxDynamicSharedMemorySize, S2_BYTES);
    k_moe<<<NE * 512, 256, S2_BYTES>>>(fc1b, fc2b);

    k_out<<<dim3(NCH / 32, NW / 32, NB * NH), dim3(32, 8)>>>(out);
}

// round 13
// speedup vs baseline: 1.3712x; 1.1375x over previous
#include <cuda_runtime.h>
#include <cuda_bf16.h>
#include <cuda_fp16.h>
#include <math.h>

// ---------------- problem constants ----------------
#define NB   2
#define NCH  128
#define NH   128
#define NW   128
#define NE   6
#define ND   6
#define NHF  512
#define NHW  (NH*NW)        // 16384
#define NTOK (NB*NH*NW)     // 32768
#define NOUT (NTOK*NCH)
#define GBLK 128            // gate blocks (256 tokens each)
#define LCAP (2*NTOK)       // per-expert list capacity

// ---------------- scratch ----------------
__device__ float g_xf[NTOK * NCH];
__device__ float g_res[NTOK * 2 * NCH];
__device__ int   g_list[NE * LCAP];
__device__ float g_gate[NE * LCAP];
__device__ int   g_cnt[NE];
__device__ float g_partW[GBLK * NE];
__device__ float g_partC[GBLK * NE];
__device__ unsigned g_done;

// fp16 weights, B layout [n][k]
__device__ __align__(16) __half g_w1t[NE * NHF * NCH];
__device__ __align__(16) __half g_w2t[NE * NHF * NCH];

// half2 gelu: tanh.approx.f16x2 does 2 tanh per MUFU op. H is fp16 anyway,
// so the f16 tanh error (~2^-11 rel) matches the existing H-quant error.
__device__ __forceinline__ unsigned gelu2h(float z0, float z1) {
    float u0 = 0.7978845608028654f * z0 * (1.0f + 0.044715f * z0 * z0);
    float u1 = 0.7978845608028654f * z1 * (1.0f + 0.044715f * z1 * z1);
    __half2 u2 = __floats2half2_rn(u0, u1);
    unsigned t;
    asm("tanh.approx.f16x2 %0, %1;" : "=r"(t) : "r"(*(unsigned*)&u2));
    __half2 zh = __floats2half2_rn(0.5f * z0, 0.5f * z1);   // 0.5*z packed
    __half2 h2 = __hfma2(zh, *(__half2*)&t, zh);            // 0.5z*t + 0.5z
    return *(unsigned*)&h2;
}
__device__ __forceinline__ unsigned pack2h(float a0, float a1) {
    __half2 h = __floats2half2_rn(a0, a1);
    return *(unsigned*)&h;
}
__device__ __forceinline__ void mma16816h(float* c, const unsigned* a, const unsigned* b) {
    asm volatile("mma.sync.aligned.m16n8k16.row.col.f32.f16.f16.f32 "
                 "{%0,%1,%2,%3}, {%4,%5,%6,%7}, {%8,%9}, {%0,%1,%2,%3};"
                 : "+f"(c[0]), "+f"(c[1]), "+f"(c[2]), "+f"(c[3])
                 : "r"(a[0]), "r"(a[1]), "r"(a[2]), "r"(a[3]),
                   "r"(b[0]), "r"(b[1]));
}
__device__ __forceinline__ void ldm_x4(unsigned* r, unsigned addr) {
    asm volatile("ldmatrix.sync.aligned.m8n8.x4.shared.b16 {%0,%1,%2,%3}, [%4];"
                 : "=r"(r[0]), "=r"(r[1]), "=r"(r[2]), "=r"(r[3]) : "r"(addr));
}
__device__ __forceinline__ unsigned smem_u32(const void* p) {
    unsigned a;
    asm("{ .reg .u64 t; cvta.to.shared.u64 t, %1; cvt.u32.u64 %0, t; }" : "=r"(a) : "l"(p));
    return a;
}
#define CP16(dst, src) \
    asm volatile("cp.async.cg.shared.global [%0], [%1], 16;" :: "r"(dst), "l"(src))
#define CP_COMMIT() asm volatile("cp.async.commit_group;" ::: "memory")
#define CP_WAIT(n)  asm volatile("cp.async.wait_group %0;" :: "n"(n) : "memory")

// ---------------- kernel 1: zero counters only ----------------
__global__ void k_init() {
    int t = threadIdx.x;
    if (t < NE) g_cnt[t] = 0;
    if (t == 31) g_done = 0;
}

// ---------------- kernel 2: fused gating + transpose + weight prep ----------
// grid split: [0, GBLK) gate | [GBLK, GBLK+TPBLK) transpose | rest weight prep
#define TPBLK 4096
#define W1ELEM (NE * NHF * NCH)
__global__ void __launch_bounds__(256)
k_pre(const float* __restrict__ x, const float* __restrict__ prompt,
      const float* __restrict__ de_cls, const float* __restrict__ w_g,
      const float* __restrict__ gboost, const float* __restrict__ degra_w,
      const float* __restrict__ degra_b,
      const float* __restrict__ fc1w, const float* __restrict__ fc2w,
      float* __restrict__ out, int out_size) {
    int bid = blockIdx.x;
    int tid = threadIdx.x;

    if (bid < GBLK) {
        // ---------- gating ----------
        __shared__ float wg_s[NCH * NE];
        __shared__ float bias_s[NE];
        __shared__ float wsum[8][NE];
        __shared__ int   wcnt[8][NE];
        __shared__ unsigned is_last_s;
        int warp = tid >> 5, lane = tid & 31;
        int n = bid * 256 + tid;
        int b = n >> 14;              // whole block shares one b

        for (int i = tid; i < NCH * NE; i += 256) wg_s[i] = w_g[i];

        if (warp < NE) {
            int e = warp;
            float s1 = 0.f;
#pragma unroll
            for (int q = 0; q < 4; q++) {
                int c = lane + q * 32;
                s1 += prompt[b * NCH + c] * w_g[(NCH + c) * NE + e];
            }
            float s2 = (lane < ND) ? de_cls[b * ND + lane] * degra_w[lane * NE + e] : 0.f;
            for (int off = 16; off; off >>= 1) {
                s1 += __shfl_down_sync(0xffffffffu, s1, off);
                s2 += __shfl_down_sync(0xffffffffu, s2, off);
            }
            if (lane == 0) bias_s[e] = s1 + gboost[0] * (s2 + degra_b[e]);
        }
        __syncthreads();

        int hw = n & (NHW - 1);
        float acc[NE];
#pragma unroll
        for (int e = 0; e < NE; e++) acc[e] = bias_s[e];
        const float* xb = x + (size_t)b * NCH * NHW + hw;
#pragma unroll 4
        for (int c = 0; c < NCH; c++) {
            float xv = xb[(size_t)c * NHW];
#pragma unroll
            for (int e = 0; e < NE; e++) acc[e] += xv * wg_s[c * NE + e];
        }
        int i0 = 0; float v0 = acc[0];
#pragma unroll
        for (int e = 1; e < NE; e++) if (acc[e] > v0) { v0 = acc[e]; i0 = e; }
        int i1 = (i0 == 0) ? 1 : 0; float v1 = acc[i1];
#pragma unroll
        for (int e = 0; e < NE; e++)
            if (e != i0 && acc[e] > v1) { v1 = acc[e]; i1 = e; }
        float g0 = 1.f / (1.f + expf(v1 - v0));
        float g1 = 1.f - g0;

        int p0 = atomicAdd(&g_cnt[i0], 1);
        g_list[i0 * LCAP + p0] = n * 2 + 0;
        g_gate[i0 * LCAP + p0] = g0;
        int p1 = atomicAdd(&g_cnt[i1], 1);
        g_list[i1 * LCAP + p1] = n * 2 + 1;
        g_gate[i1 * LCAP + p1] = g1;

#pragma unroll
        for (int e = 0; e < NE; e++) {
            float gv = (i0 == e ? g0 : 0.f) + (i1 == e ? g1 : 0.f);
            int   cv = (i0 == e) + (i1 == e);
            for (int off = 16; off; off >>= 1) {
                gv += __shfl_down_sync(0xffffffffu, gv, off);
                cv += __shfl_down_sync(0xffffffffu, cv, off);
            }
            if (lane == 0) { wsum[warp][e] = gv; wcnt[warp][e] = cv; }
        }
        __syncthreads();
        if (tid < NE) {
            float s = 0.f; int c = 0;
#pragma unroll
            for (int w = 0; w < 8; w++) { s += wsum[w][tid]; c += wcnt[w][tid]; }
            g_partW[bid * NE + tid] = s;
            g_partC[bid * NE + tid] = (float)c;
        }
        __threadfence();
        __syncthreads();
        if (tid == 0) is_last_s = (atomicAdd(&g_done, 1u) == GBLK - 1);
        __syncthreads();
        if (is_last_s) {
            if (warp < NE) {
                float sW = g_partW[lane * NE + warp] + g_partW[(lane + 32) * NE + warp]
                         + g_partW[(lane + 64) * NE + warp] + g_partW[(lane + 96) * NE + warp];
                float sC = g_partC[lane * NE + warp] + g_partC[(lane + 32) * NE + warp]
                         + g_partC[(lane + 64) * NE + warp] + g_partC[(lane + 96) * NE + warp];
                for (int off = 16; off; off >>= 1) {
                    sW += __shfl_down_sync(0xffffffffu, sW, off);
                    sC += __shfl_down_sync(0xffffffffu, sC, off);
                }
                if (lane == 0) { wsum[0][warp] = sW; wsum[1][warp] = sC; }
            }
            __syncthreads();
            if (tid == 0 && out_size > NOUT) {
                float mW = 0.f, mC = 0.f;
                for (int e = 0; e < NE; e++) { mW += wsum[0][e]; mC += wsum[1][e]; }
                mW /= NE; mC /= NE;
                float vW = 0.f, vC = 0.f;
                for (int e = 0; e < NE; e++) {
                    vW += (wsum[0][e] - mW) * (wsum[0][e] - mW);
                    vC += (wsum[1][e] - mC) * (wsum[1][e] - mC);
                }
                vW /= (NE - 1); vC /= (NE - 1);
                out[NOUT] = vW / (mW * mW + 1e-10f) + vC / (mC * mC + 1e-10f);
            }
        }
    } else if (bid < GBLK + TPBLK) {
        // ---------- transpose x -> g_xf ----------
        __shared__ float tile[32][33];
        int tb = bid - GBLK;
        int cx = tb & 3, wy = (tb >> 2) & 3, bh = tb >> 4;
        int b = bh / NH, h = bh % NH;
        int c0 = cx * 32, w0 = wy * 32;
        int tx = tid & 31, ty = tid >> 5;
        for (int i = ty; i < 32; i += 8)
            tile[i][tx] = x[(((size_t)b * NCH + c0 + i) * NH + h) * NW + w0 + tx];
        __syncthreads();
        for (int i = ty; i < 32; i += 8)
            g_xf[((size_t)(b * NHW + h * NW + w0 + i)) * NCH + c0 + tx] = tile[tx][i];
    } else {
        // ---------- weight prep ----------
        int idx = (bid - GBLK - TPBLK) * 256 + tid;
        if (idx < W1ELEM) {
            int e = idx >> 16, rem = idx & 65535;
            int n = rem >> 7, k = rem & 127;
            g_w1t[idx] = __float2half_rn(fc1w[((size_t)e * NCH + k) * NHF + n]);
        } else {
            int j = idx - W1ELEM;
            if (j < W1ELEM) {
                int e = j >> 16, rem = j & 65535;
                int jc = rem >> 13, r2 = rem & 8191;
                int c = r2 >> 6, k = r2 & 63;
                g_w2t[j] = __float2half_rn(fc2w[((size_t)e * NHF + jc * 64 + k) * NCH + c]);
            }
        }
    }
}

// ---------------- kernel 3: fp16 mma MoE, m32 warp tiles, half2 gelu ---------
// SMEM map (bytes):
#define S2_X     0                     // [128][136] half = 34816
#define S2_W1    34816                 // 2 buffers x [64][136] half = 2*17408
#define S2_W2    69632                 // [128][72] half = 18432
#define S2_H     88064                 // [128][72] half = 18432
#define S2_SLOT  106496
#define S2_GATE  107008
#define S2_BYTES 107520

__global__ void __launch_bounds__(256, 2)
k_moe(const float* __restrict__ fc1b, const float* __restrict__ fc2b) {
    int e    = blockIdx.x >> 9;
    int tile = blockIdx.x & 511;
    int cnt  = g_cnt[e];
    int row0 = tile << 7;
    if (row0 >= cnt) return;

    extern __shared__ char sm[];
    unsigned sb = smem_u32(sm);
    __half* Hs = (__half*)(sm + S2_H);
    int*   slot_s = (int*)(sm + S2_SLOT);
    float* gate_s = (float*)(sm + S2_GATE);

    int tid = threadIdx.x;
    int wid = tid >> 5, lt = tid & 31;
    int qr = lt >> 2, qc = lt & 3;
    int mb  = (wid & 3) * 32;          // warp m-block (32 rows)
    int nb1 = (wid >> 2) * 32;         // GEMM1 n-block (32 of 64)
    int nb2 = (wid >> 2) * 64;         // GEMM2 n-block (64 of 128)
    int lrow = lt & 15;
    int lcol = (lt & 16) >> 1;         // 0 or 8 (halfs)

    const __half* w1g = g_w1t + (size_t)e * NHF * NCH;
    const __half* w2g = g_w2t + (size_t)e * NHF * NCH;

    // prefetch W1 chunk 0 into buffer 0
    {
        unsigned d = sb + S2_W1;
#pragma unroll
        for (int it = 0; it < 4; it++) {
            int u = tid + it * 256;              // 0..1023
            int n1 = u >> 4, k16 = u & 15;
            CP16(d + (unsigned)(n1 * 136 + k16 * 8) * 2, w1g + n1 * NCH + k16 * 8);
        }
        CP_COMMIT();
    }

    if (tid < 128) {
        int r = row0 + tid;
        if (r < cnt) { slot_s[tid] = g_list[e * LCAP + r]; gate_s[tid] = g_gate[e * LCAP + r]; }
        else         { slot_s[tid] = -1; gate_s[tid] = 0.f; }
    }
    __syncthreads();

    // gather X -> fp16
#pragma unroll
    for (int it = 0; it < 8; it++) {
        int idx = tid + it * 256;
        int r = idx >> 4, c8 = idx & 15;
        float v[8];
        int s = slot_s[r];
        if (s >= 0) {
            const float4* src = (const float4*)(g_xf + (size_t)(s >> 1) * NCH + c8 * 8);
            float4 a = src[0], b = src[1];
            v[0]=a.x; v[1]=a.y; v[2]=a.z; v[3]=a.w; v[4]=b.x; v[5]=b.y; v[6]=b.z; v[7]=b.w;
        } else {
#pragma unroll
            for (int q = 0; q < 8; q++) v[q] = 0.f;
        }
        uint4 U;
        U.x = pack2h(v[0], v[1]);
        U.y = pack2h(v[2], v[3]);
        U.z = pack2h(v[4], v[5]);
        U.w = pack2h(v[6], v[7]);
        *(uint4*)((__half*)(sm + S2_X) + r * 136 + c8 * 8) = U;
    }

    float acc2[2][8][4];
#pragma unroll
    for (int i = 0; i < 2; i++)
#pragma unroll
        for (int j = 0; j < 8; j++)
#pragma unroll
            for (int q = 0; q < 4; q++) acc2[i][j][q] = 0.f;

    // per-lane ldmatrix base addresses (bytes)
    unsigned aX  = sb + S2_X  + (unsigned)((mb + lrow) * 136 + lcol) * 2;
    unsigned aH  = sb + S2_H  + (unsigned)((mb + lrow) * 72  + lcol) * 2;
    unsigned bW2 = sb + S2_W2 + (unsigned)((nb2 + lrow) * 72 + lcol) * 2;

    for (int jc = 0; jc < 8; jc++) {
        int cur = jc & 1;
        unsigned bW1 = sb + S2_W1 + cur * 17408 + (unsigned)((nb1 + lrow) * 136 + lcol) * 2;

        // issue W2(jc) async
        {
            unsigned d2 = sb + S2_W2;
            const __half* s2 = w2g + jc * 8192;
#pragma unroll
            for (int it = 0; it < 4; it++) {
                int u = tid + it * 256;
                int n2 = u >> 3, k8 = u & 7;
                CP16(d2 + (unsigned)(n2 * 72 + k8 * 8) * 2, s2 + n2 * 64 + k8 * 8);
            }
            CP_COMMIT();
        }
        CP_WAIT(1);              // W1(jc) arrived
        __syncthreads();

        // GEMM1: warp tile m32 x n32, A reused across both n16 groups
        float acc1[2][4][4];
#pragma unroll
        for (int i = 0; i < 2; i++)
#pragma unroll
            for (int j = 0; j < 4; j++)
#pragma unroll
                for (int q = 0; q < 4; q++) acc1[i][j][q] = 0.f;

#pragma unroll
        for (int kt = 0; kt < 8; kt++) {
            unsigned a0[4], a1[4];
            ldm_x4(a0, aX + kt * 32);
            ldm_x4(a1, aX + 16 * 136 * 2 + kt * 32);
#pragma unroll
            for (int j2 = 0; j2 < 2; j2++) {
                unsigned r[4];
                ldm_x4(r, bW1 + (unsigned)(j2 * 16 * 136) * 2 + kt * 32);
                unsigned b0[2] = { r[0], r[2] };
                unsigned b1[2] = { r[1], r[3] };
                mma16816h(acc1[0][2 * j2],     a0, b0);
                mma16816h(acc1[0][2 * j2 + 1], a0, b1);
                mma16816h(acc1[1][2 * j2],     a1, b0);
                mma16816h(acc1[1][2 * j2 + 1], a1, b1);
            }
        }
        // bias + half2 gelu -> H
#pragma unroll
        for (int i = 0; i < 2; i++)
#pragma unroll
            for (int j = 0; j < 4; j++) {
                int n = nb1 + j * 8 + qc * 2;
                float2 b1v = *(const float2*)(fc1b + e * NHF + jc * 64 + n);
                *(unsigned*)(Hs + (mb + i * 16 + qr) * 72 + n) =
                    gelu2h(acc1[i][j][0] + b1v.x, acc1[i][j][1] + b1v.y);
                *(unsigned*)(Hs + (mb + i * 16 + qr + 8) * 72 + n) =
                    gelu2h(acc1[i][j][2] + b1v.x, acc1[i][j][3] + b1v.y);
            }
        CP_WAIT(0);              // W2(jc) arrived
        __syncthreads();         // H visible + W2 visible

        // prefetch W1(jc+1) during GEMM2
        if (jc < 7) {
            unsigned d = sb + S2_W1 + (1 - cur) * 17408;
            const __half* s1 = w1g + (jc + 1) * 64 * NCH;
#pragma unroll
            for (int it = 0; it < 4; it++) {
                int u = tid + it * 256;
                int n1 = u >> 4, k16 = u & 15;
                CP16(d + (unsigned)(n1 * 136 + k16 * 8) * 2, s1 + n1 * NCH + k16 * 8);
            }
            CP_COMMIT();
        }

        // GEMM2: warp tile m32 x n64
#pragma unroll
        for (int kt = 0; kt < 4; kt++) {
            unsigned a0[4], a1[4];
            ldm_x4(a0, aH + kt * 32);
            ldm_x4(a1, aH + 16 * 72 * 2 + kt * 32);
#pragma unroll
            for (int j2 = 0; j2 < 4; j2++) {
                unsigned r[4];
                ldm_x4(r, bW2 + (unsigned)(j2 * 16 * 72) * 2 + kt * 32);
                unsigned b0[2] = { r[0], r[2] };
                unsigned b1[2] = { r[1], r[3] };
                mma16816h(acc2[0][2 * j2],     a0, b0);
                mma16816h(acc2[0][2 * j2 + 1], a0, b1);
                mma16816h(acc2[1][2 * j2],     a1, b0);
                mma16816h(acc2[1][2 * j2 + 1], a1, b1);
            }
        }
        __syncthreads();         // protect H + W2 for next chunk
    }

    // epilogue: gate * exp(out + b2) -> g_res
#pragma unroll
    for (int i = 0; i < 2; i++) {
        int mAr = mb + i * 16 + qr, mBr = mAr + 8;
        int sA = slot_s[mAr], sB = slot_s[mBr];
        float gA = gate_s[mAr], gB = gate_s[mBr];
#pragma unroll
        for (int j = 0; j < 8; j++) {
            int c = nb2 + j * 8 + qc * 2;
            float2 b2 = *(const float2*)(fc2b + e * NCH + c);
            if (sA >= 0) {
                float2 o;
                o.x = gA * __expf(acc2[i][j][0] + b2.x);
                o.y = gA * __expf(acc2[i][j][1] + b2.y);
                *(float2*)(g_res + (size_t)sA * NCH + c) = o;
            }
            if (sB >= 0) {
                float2 o;
                o.x = gB * __expf(acc2[i][j][2] + b2.x);
                o.y = gB * __expf(acc2[i][j][3] + b2.y);
                *(float2*)(g_res + (size_t)sB * NCH + c) = o;
            }
        }
    }
}

// ---------------- kernel 4: combine + log + transpose back ----------------
__global__ void k_out(float* __restrict__ out) {
    __shared__ float tile[32][33];
    int bh = blockIdx.z;
    int b = bh / NH, h = bh % NH;
    int c0 = blockIdx.x * 32, w0 = blockIdx.y * 32;
    int tx = threadIdx.x, ty = threadIdx.y;
    for (int i = ty; i < 32; i += 8) {
        size_t base = (size_t)(b * NHW + h * NW + w0 + i) * 2 * NCH;
        float v = g_res[base + c0 + tx] + g_res[base + NCH + c0 + tx];
        if (v == 0.f) v = 2.2204460492503131e-16f;
        tile[i][tx] = __logf(v);
    }
    __syncthreads();
    for (int i = ty; i < 32; i += 8)
        out[(((size_t)b * NCH + c0 + i) * NH + h) * NW + w0 + tx] = tile[tx][i];
}

// ---------------- launch ----------------
extern "C" void kernel_launch(void* const* d_in, const int* in_sizes, int n_in,
                              void* d_out, int out_size) {
    (void)in_sizes; (void)n_in;
    const float* x       = (const float*)d_in[0];
    const float* prompt  = (const float*)d_in[1];
    const float* de_cls  = (const float*)d_in[2];
    const float* w_g     = (const float*)d_in[3];
    const float* gboost  = (const float*)d_in[4];
    const float* degra_w = (const float*)d_in[5];
    const float* degra_b = (const float*)d_in[6];
    const float* fc1w    = (const float*)d_in[7];
    const float* fc1b    = (const float*)d_in[8];
    const float* fc2w    = (const float*)d_in[9];
    const float* fc2b    = (const float*)d_in[10];
    float* out = (float*)d_out;

    k_init<<<1, 32>>>();
    k_pre<<<GBLK + TPBLK + 3072, 256>>>(x, prompt, de_cls, w_g, gboost,
                                        degra_w, degra_b, fc1w, fc2w,
                                        out, out_size);

    cudaFuncSetAttribute(k_moe, cudaFuncAttributeMaxDynamicSharedMemorySize, S2_BYTES);
    k_moe<<<NE * 512, 256, S2_BYTES>>>(fc1b, fc2b);

    k_out<<<dim3(NCH / 32, NW / 32, NB * NH), dim3(32, 8)>>>(out);
}

// round 15
// speedup vs baseline: 1.3971x; 1.0188x over previous
#include <cuda_runtime.h>
#include <cuda_bf16.h>
#include <cuda_fp16.h>
#include <math.h>

// ---------------- problem constants ----------------
#define NB   2
#define NCH  128
#define NH   128
#define NW   128
#define NE   6
#define ND   6
#define NHF  512
#define NHW  (NH*NW)        // 16384
#define NTOK (NB*NH*NW)     // 32768
#define NOUT (NTOK*NCH)
#define GBLK 128            // gate blocks (256 tokens each)
#define LCAP (2*NTOK)       // per-expert list capacity

// ---------------- scratch ----------------
__device__ __align__(16) __half g_xf[NTOK * NCH];        // fp16 activations
__device__ __align__(16) __half g_res[NTOK * 2 * NCH];   // fp16 out+b2 (pre-exp!)
__device__ float g_gates[NTOK * 2];                      // fp32 gate per slot
__device__ int   g_list[NE * LCAP];
__device__ float g_gate[NE * LCAP];
__device__ int   g_cnt[NE];
__device__ float g_partW[GBLK * NE];
__device__ float g_partC[GBLK * NE];
__device__ unsigned g_done;

// fp16 weights, B layout [n][k]
__device__ __align__(16) __half g_w1t[NE * NHF * NCH];
__device__ __align__(16) __half g_w2t[NE * NHF * NCH];

// half2 gelu via tanh.approx.f16x2 (2 tanh per MUFU op)
__device__ __forceinline__ unsigned gelu2h(float z0, float z1) {
    float u0 = 0.7978845608028654f * z0 * (1.0f + 0.044715f * z0 * z0);
    float u1 = 0.7978845608028654f * z1 * (1.0f + 0.044715f * z1 * z1);
    __half2 u2 = __floats2half2_rn(u0, u1);
    unsigned t;
    asm("tanh.approx.f16x2 %0, %1;" : "=r"(t) : "r"(*(unsigned*)&u2));
    __half2 zh = __floats2half2_rn(0.5f * z0, 0.5f * z1);
    __half2 h2 = __hfma2(zh, *(__half2*)&t, zh);
    return *(unsigned*)&h2;
}
__device__ __forceinline__ unsigned pack2h(float a0, float a1) {
    __half2 h = __floats2half2_rn(a0, a1);
    return *(unsigned*)&h;
}
__device__ __forceinline__ void mma16816h(float* c, const unsigned* a, const unsigned* b) {
    asm volatile("mma.sync.aligned.m16n8k16.row.col.f32.f16.f16.f32 "
                 "{%0,%1,%2,%3}, {%4,%5,%6,%7}, {%8,%9}, {%0,%1,%2,%3};"
                 : "+f"(c[0]), "+f"(c[1]), "+f"(c[2]), "+f"(c[3])
                 : "r"(a[0]), "r"(a[1]), "r"(a[2]), "r"(a[3]),
                   "r"(b[0]), "r"(b[1]));
}
__device__ __forceinline__ void ldm_x4(unsigned* r, unsigned addr) {
    asm volatile("ldmatrix.sync.aligned.m8n8.x4.shared.b16 {%0,%1,%2,%3}, [%4];"
                 : "=r"(r[0]), "=r"(r[1]), "=r"(r[2]), "=r"(r[3]) : "r"(addr));
}
__device__ __forceinline__ unsigned smem_u32(const void* p) {
    unsigned a;
    asm("{ .reg .u64 t; cvta.to.shared.u64 t, %1; cvt.u32.u64 %0, t; }" : "=r"(a) : "l"(p));
    return a;
}
#define CP16(dst, src) \
    asm volatile("cp.async.cg.shared.global [%0], [%1], 16;" :: "r"(dst), "l"(src))
#define CP_COMMIT() asm volatile("cp.async.commit_group;" ::: "memory")
#define CP_WAIT(n)  asm volatile("cp.async.wait_group %0;" :: "n"(n) : "memory")

// ---------------- kernel 1: zero counters only ----------------
__global__ void k_init() {
    int t = threadIdx.x;
    if (t < NE) g_cnt[t] = 0;
    if (t == 31) g_done = 0;
}

// ---------------- kernel 2: fused gating + transpose + weight prep ----------
#define TPBLK 4096
#define W1ELEM (NE * NHF * NCH)
__global__ void __launch_bounds__(256)
k_pre(const float* __restrict__ x, const float* __restrict__ prompt,
      const float* __restrict__ de_cls, const float* __restrict__ w_g,
      const float* __restrict__ gboost, const float* __restrict__ degra_w,
      const float* __restrict__ degra_b,
      const float* __restrict__ fc1w, const float* __restrict__ fc2w,
      float* __restrict__ out, int out_size) {
    int bid = blockIdx.x;
    int tid = threadIdx.x;

    if (bid < GBLK) {
        // ---------- gating ----------
        __shared__ float wg_s[NCH * NE];
        __shared__ float bias_s[NE];
        __shared__ float wsum[8][NE];
        __shared__ int   wcnt[8][NE];
        __shared__ unsigned is_last_s;
        int warp = tid >> 5, lane = tid & 31;
        int n = bid * 256 + tid;
        int b = n >> 14;

        for (int i = tid; i < NCH * NE; i += 256) wg_s[i] = w_g[i];

        if (warp < NE) {
            int e = warp;
            float s1 = 0.f;
#pragma unroll
            for (int q = 0; q < 4; q++) {
                int c = lane + q * 32;
                s1 += prompt[b * NCH + c] * w_g[(NCH + c) * NE + e];
            }
            float s2 = (lane < ND) ? de_cls[b * ND + lane] * degra_w[lane * NE + e] : 0.f;
            for (int off = 16; off; off >>= 1) {
                s1 += __shfl_down_sync(0xffffffffu, s1, off);
                s2 += __shfl_down_sync(0xffffffffu, s2, off);
            }
            if (lane == 0) bias_s[e] = s1 + gboost[0] * (s2 + degra_b[e]);
        }
        __syncthreads();

        int hw = n & (NHW - 1);
        float acc[NE];
#pragma unroll
        for (int e = 0; e < NE; e++) acc[e] = bias_s[e];
        const float* xb = x + (size_t)b * NCH * NHW + hw;
#pragma unroll 4
        for (int c = 0; c < NCH; c++) {
            float xv = xb[(size_t)c * NHW];
#pragma unroll
            for (int e = 0; e < NE; e++) acc[e] += xv * wg_s[c * NE + e];
        }
        int i0 = 0; float v0 = acc[0];
#pragma unroll
        for (int e = 1; e < NE; e++) if (acc[e] > v0) { v0 = acc[e]; i0 = e; }
        int i1 = (i0 == 0) ? 1 : 0; float v1 = acc[i1];
#pragma unroll
        for (int e = 0; e < NE; e++)
            if (e != i0 && acc[e] > v1) { v1 = acc[e]; i1 = e; }
        float g0 = 1.f / (1.f + expf(v1 - v0));
        float g1 = 1.f - g0;

        int p0 = atomicAdd(&g_cnt[i0], 1);
        g_list[i0 * LCAP + p0] = n * 2 + 0;
        g_gate[i0 * LCAP + p0] = g0;
        int p1 = atomicAdd(&g_cnt[i1], 1);
        g_list[i1 * LCAP + p1] = n * 2 + 1;
        g_gate[i1 * LCAP + p1] = g1;

#pragma unroll
        for (int e = 0; e < NE; e++) {
            float gv = (i0 == e ? g0 : 0.f) + (i1 == e ? g1 : 0.f);
            int   cv = (i0 == e) + (i1 == e);
            for (int off = 16; off; off >>= 1) {
                gv += __shfl_down_sync(0xffffffffu, gv, off);
                cv += __shfl_down_sync(0xffffffffu, cv, off);
            }
            if (lane == 0) { wsum[warp][e] = gv; wcnt[warp][e] = cv; }
        }
        __syncthreads();
        if (tid < NE) {
            float s = 0.f; int c = 0;
#pragma unroll
            for (int w = 0; w < 8; w++) { s += wsum[w][tid]; c += wcnt[w][tid]; }
            g_partW[bid * NE + tid] = s;
            g_partC[bid * NE + tid] = (float)c;
        }
        __threadfence();
        __syncthreads();
        if (tid == 0) is_last_s = (atomicAdd(&g_done, 1u) == GBLK - 1);
        __syncthreads();
        if (is_last_s) {
            if (warp < NE) {
                float sW = g_partW[lane * NE + warp] + g_partW[(lane + 32) * NE + warp]
                         + g_partW[(lane + 64) * NE + warp] + g_partW[(lane + 96) * NE + warp];
                float sC = g_partC[lane * NE + warp] + g_partC[(lane + 32) * NE + warp]
                         + g_partC[(lane + 64) * NE + warp] + g_partC[(lane + 96) * NE + warp];
                for (int off = 16; off; off >>= 1) {
                    sW += __shfl_down_sync(0xffffffffu, sW, off);
                    sC += __shfl_down_sync(0xffffffffu, sC, off);
                }
                if (lane == 0) { wsum[0][warp] = sW; wsum[1][warp] = sC; }
            }
            __syncthreads();
            if (tid == 0 && out_size > NOUT) {
                float mW = 0.f, mC = 0.f;
                for (int e = 0; e < NE; e++) { mW += wsum[0][e]; mC += wsum[1][e]; }
                mW /= NE; mC /= NE;
                float vW = 0.f, vC = 0.f;
                for (int e = 0; e < NE; e++) {
                    vW += (wsum[0][e] - mW) * (wsum[0][e] - mW);
                    vC += (wsum[1][e] - mC) * (wsum[1][e] - mC);
                }
                vW /= (NE - 1); vC /= (NE - 1);
                out[NOUT] = vW / (mW * mW + 1e-10f) + vC / (mC * mC + 1e-10f);
            }
        }
    } else if (bid < GBLK + TPBLK) {
        // ---------- transpose x -> g_xf (fp16; zero added error: X is fp16
        // quantized in k_moe anyway) ----------
        __shared__ float tile[32][33];
        int tb = bid - GBLK;
        int cx = tb & 3, wy = (tb >> 2) & 3, bh = tb >> 4;
        int b = bh / NH, h = bh % NH;
        int c0 = cx * 32, w0 = wy * 32;
        int tx = tid & 31, ty = tid >> 5;
        for (int i = ty; i < 32; i += 8)
            tile[i][tx] = x[(((size_t)b * NCH + c0 + i) * NH + h) * NW + w0 + tx];
        __syncthreads();
        for (int i = ty; i < 32; i += 8)
            g_xf[((size_t)(b * NHW + h * NW + w0 + i)) * NCH + c0 + tx] =
                __float2half_rn(tile[tx][i]);
    } else {
        // ---------- weight prep ----------
        int idx = (bid - GBLK - TPBLK) * 256 + tid;
        if (idx < W1ELEM) {
            int e = idx >> 16, rem = idx & 65535;
            int n = rem >> 7, k = rem & 127;
            g_w1t[idx] = __float2half_rn(fc1w[((size_t)e * NCH + k) * NHF + n]);
        } else {
            int j = idx - W1ELEM;
            if (j < W1ELEM) {
                int e = j >> 16, rem = j & 65535;
                int jc = rem >> 13, r2 = rem & 8191;
                int c = r2 >> 6, k = r2 & 63;
                g_w2t[j] = __float2half_rn(fc2w[((size_t)e * NHF + jc * 64 + k) * NCH + c]);
            }
        }
    }
}

// ---------------- kernel 3: fp16 mma MoE, m32 warp tiles ---------------------
// SMEM map (bytes):
#define S2_X     0                     // [128][136] half = 34816
#define S2_W1    34816                 // 2 buffers x [64][136] half = 2*17408
#define S2_W2    69632                 // [128][72] half = 18432
#define S2_H     88064                 // [128][72] half = 18432
#define S2_SLOT  106496
#define S2_GATE  107008
#define S2_BYTES 107520

__global__ void __launch_bounds__(256, 2)
k_moe(const float* __restrict__ fc1b, const float* __restrict__ fc2b) {
    int e    = blockIdx.x >> 9;
    int tile = blockIdx.x & 511;
    int cnt  = g_cnt[e];
    int row0 = tile << 7;
    if (row0 >= cnt) return;

    extern __shared__ char sm[];
    unsigned sb = smem_u32(sm);
    __half* Hs = (__half*)(sm + S2_H);
    int*   slot_s = (int*)(sm + S2_SLOT);
    float* gate_s = (float*)(sm + S2_GATE);

    int tid = threadIdx.x;
    int wid = tid >> 5, lt = tid & 31;
    int qr = lt >> 2, qc = lt & 3;
    int mb  = (wid & 3) * 32;          // warp m-block (32 rows)
    int nb1 = (wid >> 2) * 32;         // GEMM1 n-block
    int nb2 = (wid >> 2) * 64;         // GEMM2 n-block
    int lrow = lt & 15;
    int lcol = (lt & 16) >> 1;

    const __half* w1g = g_w1t + (size_t)e * NHF * NCH;
    const __half* w2g = g_w2t + (size_t)e * NHF * NCH;

    // prefetch W1 chunk 0 into buffer 0
    {
        unsigned d = sb + S2_W1;
#pragma unroll
        for (int it = 0; it < 4; it++) {
            int u = tid + it * 256;
            int n1 = u >> 4, k16 = u & 15;
            CP16(d + (unsigned)(n1 * 136 + k16 * 8) * 2, w1g + n1 * NCH + k16 * 8);
        }
        CP_COMMIT();
    }

    if (tid < 128) {
        int r = row0 + tid;
        if (r < cnt) {
            int s = g_list[e * LCAP + r];
            float g = g_gate[e * LCAP + r];
            slot_s[tid] = s; gate_s[tid] = g;
            g_gates[s] = g;                       // per-slot gate for k_out
        } else { slot_s[tid] = -1; gate_s[tid] = 0.f; }
    }
    __syncthreads();

    // gather X (already fp16) -> smem, straight uint4 copies
#pragma unroll
    for (int it = 0; it < 8; it++) {
        int idx = tid + it * 256;           // 0..2047
        int r = idx >> 4, c8 = idx & 15;
        uint4 U = make_uint4(0u, 0u, 0u, 0u);
        int s = slot_s[r];
        if (s >= 0)
            U = *(const uint4*)(g_xf + (size_t)(s >> 1) * NCH + c8 * 8);
        *(uint4*)((__half*)(sm + S2_X) + r * 136 + c8 * 8) = U;
    }

    float acc2[2][8][4];
#pragma unroll
    for (int i = 0; i < 2; i++)
#pragma unroll
        for (int j = 0; j < 8; j++)
#pragma unroll
            for (int q = 0; q < 4; q++) acc2[i][j][q] = 0.f;

    unsigned aX  = sb + S2_X  + (unsigned)((mb + lrow) * 136 + lcol) * 2;
    unsigned aH  = sb + S2_H  + (unsigned)((mb + lrow) * 72  + lcol) * 2;
    unsigned bW2 = sb + S2_W2 + (unsigned)((nb2 + lrow) * 72 + lcol) * 2;

    for (int jc = 0; jc < 8; jc++) {
        int cur = jc & 1;
        unsigned bW1 = sb + S2_W1 + cur * 17408 + (unsigned)((nb1 + lrow) * 136 + lcol) * 2;

        // issue W2(jc) async
        {
            unsigned d2 = sb + S2_W2;
            const __half* s2 = w2g + jc * 8192;
#pragma unroll
            for (int it = 0; it < 4; it++) {
                int u = tid + it * 256;
                int n2 = u >> 3, k8 = u & 7;
                CP16(d2 + (unsigned)(n2 * 72 + k8 * 8) * 2, s2 + n2 * 64 + k8 * 8);
            }
            CP_COMMIT();
        }
        CP_WAIT(1);
        __syncthreads();

        // GEMM1: warp tile m32 x n32
        float acc1[2][4][4];
#pragma unroll
        for (int i = 0; i < 2; i++)
#pragma unroll
            for (int j = 0; j < 4; j++)
#pragma unroll
                for (int q = 0; q < 4; q++) acc1[i][j][q] = 0.f;

#pragma unroll
        for (int kt = 0; kt < 8; kt++) {
            unsigned a0[4], a1[4];
            ldm_x4(a0, aX + kt * 32);
            ldm_x4(a1, aX + 16 * 136 * 2 + kt * 32);
#pragma unroll
            for (int j2 = 0; j2 < 2; j2++) {
                unsigned r[4];
                ldm_x4(r, bW1 + (unsigned)(j2 * 16 * 136) * 2 + kt * 32);
                unsigned b0[2] = { r[0], r[2] };
                unsigned b1[2] = { r[1], r[3] };
                mma16816h(acc1[0][2 * j2],     a0, b0);
                mma16816h(acc1[0][2 * j2 + 1], a0, b1);
                mma16816h(acc1[1][2 * j2],     a1, b0);
                mma16816h(acc1[1][2 * j2 + 1], a1, b1);
            }
        }
        // bias + half2 gelu -> H
#pragma unroll
        for (int i = 0; i < 2; i++)
#pragma unroll
            for (int j = 0; j < 4; j++) {
                int n = nb1 + j * 8 + qc * 2;
                float2 b1v = *(const float2*)(fc1b + e * NHF + jc * 64 + n);
                *(unsigned*)(Hs + (mb + i * 16 + qr) * 72 + n) =
                    gelu2h(acc1[i][j][0] + b1v.x, acc1[i][j][1] + b1v.y);
                *(unsigned*)(Hs + (mb + i * 16 + qr + 8) * 72 + n) =
                    gelu2h(acc1[i][j][2] + b1v.x, acc1[i][j][3] + b1v.y);
            }
        CP_WAIT(0);
        __syncthreads();

        // prefetch W1(jc+1) during GEMM2
        if (jc < 7) {
            unsigned d = sb + S2_W1 + (1 - cur) * 17408;
            const __half* s1 = w1g + (jc + 1) * 64 * NCH;
#pragma unroll
            for (int it = 0; it < 4; it++) {
                int u = tid + it * 256;
                int n1 = u >> 4, k16 = u & 15;
                CP16(d + (unsigned)(n1 * 136 + k16 * 8) * 2, s1 + n1 * NCH + k16 * 8);
            }
            CP_COMMIT();
        }

        // GEMM2: warp tile m32 x n64
#pragma unroll
        for (int kt = 0; kt < 4; kt++) {
            unsigned a0[4], a1[4];
            ldm_x4(a0, aH + kt * 32);
            ldm_x4(a1, aH + 16 * 72 * 2 + kt * 32);
#pragma unroll
            for (int j2 = 0; j2 < 4; j2++) {
                unsigned r[4];
                ldm_x4(r, bW2 + (unsigned)(j2 * 16 * 72) * 2 + kt * 32);
                unsigned b0[2] = { r[0], r[2] };
                unsigned b1[2] = { r[1], r[3] };
                mma16816h(acc2[0][2 * j2],     a0, b0);
                mma16816h(acc2[0][2 * j2 + 1], a0, b1);
                mma16816h(acc2[1][2 * j2],     a1, b0);
                mma16816h(acc2[1][2 * j2 + 1], a1, b1);
            }
        }
        __syncthreads();
    }

    // epilogue: store PRE-EXP logits (out + b2) as fp16; |out|~0.05 so fp16
    // quant abs err ~2.4e-5 in final y (vs 4.9e-4 if storing exp products)
#pragma unroll
    for (int i = 0; i < 2; i++) {
        int mAr = mb + i * 16 + qr, mBr = mAr + 8;
        int sA = slot_s[mAr], sB = slot_s[mBr];
#pragma unroll
        for (int j = 0; j < 8; j++) {
            int c = nb2 + j * 8 + qc * 2;
            float2 b2 = *(const float2*)(fc2b + e * NCH + c);
            if (sA >= 0) {
                *(unsigned*)(g_res + (size_t)sA * NCH + c) =
                    pack2h(acc2[i][j][0] + b2.x, acc2[i][j][1] + b2.y);
            }
            if (sB >= 0) {
                *(unsigned*)(g_res + (size_t)sB * NCH + c) =
                    pack2h(acc2[i][j][2] + b2.x, acc2[i][j][3] + b2.y);
            }
        }
    }
}

// ---------------- kernel 4: combine: log(g0 e^o0 + g1 e^o1) + transpose ------
__global__ void __launch_bounds__(256)
k_out(float* __restrict__ out) {
    __shared__ float tile[64][33];
    int bh = blockIdx.z;
    int b = bh / NH, h = bh % NH;
    int c0 = blockIdx.x * 64, w0 = blockIdx.y * 32;
    int tx = threadIdx.x & 31, ty = threadIdx.x >> 5;
    for (int i = ty; i < 32; i += 8) {
        int token = b * NHW + h * NW + w0 + i;
        float g0 = g_gates[token * 2];
        float g1 = g_gates[token * 2 + 1];
        size_t base = (size_t)token * 2 * NCH;
        __half2 o0 = *(const __half2*)(g_res + base + c0 + 2 * tx);
        __half2 o1 = *(const __half2*)(g_res + base + NCH + c0 + 2 * tx);
        float v0 = g0 * __expf(__low2float(o0))  + g1 * __expf(__low2float(o1));
        float v1 = g0 * __expf(__high2float(o0)) + g1 * __expf(__high2float(o1));
        if (v0 == 0.f) v0 = 2.2204460492503131e-16f;
        if (v1 == 0.f) v1 = 2.2204460492503131e-16f;
        tile[2 * tx][i]     = __logf(v0);
        tile[2 * tx + 1][i] = __logf(v1);
    }
    __syncthreads();
    for (int j = ty; j < 64; j += 8)
        out[((size_t)(b * NCH + c0 + j)) * NHW + h * NW + w0 + tx] = tile[j][tx];
}

// ---------------- launch ----------------
extern "C" void kernel_launch(void* const* d_in, const int* in_sizes, int n_in,
                              void* d_out, int out_size) {
    (void)in_sizes; (void)n_in;
    const float* x       = (const float*)d_in[0];
    const float* prompt  = (const float*)d_in[1];
    const float* de_cls  = (const float*)d_in[2];
    const float* w_g     = (const float*)d_in[3];
    const float* gboost  = (const float*)d_in[4];
    const float* degra_w = (const float*)d_in[5];
    const float* degra_b = (const float*)d_in[6];
    const float* fc1w    = (const float*)d_in[7];
    const float* fc1b    = (const float*)d_in[8];
    const float* fc2w    = (const float*)d_in[9];
    const float* fc2b    = (const float*)d_in[10];
    float* out = (float*)d_out;

    k_init<<<1, 32>>>();
    k_pre<<<GBLK + TPBLK + 3072, 256>>>(x, prompt, de_cls, w_g, gboost,
                                        degra_w, degra_b, fc1w, fc2w,
                                        out, out_size);

    cudaFuncSetAttribute(k_moe, cudaFuncAttributeMaxDynamicSharedMemorySize, S2_BYTES);
    k_moe<<<NE * 512, 256, S2_BYTES>>>(fc1b, fc2b);

    k_out<<<dim3(NCH / 64, NW / 32, NB * NH), 256>>>(out);
}

// round 16
// speedup vs baseline: 1.4218x; 1.0177x over previous
#include <cuda_runtime.h>
#include <cuda_bf16.h>
#include <cuda_fp16.h>
#include <math.h>

// ---------------- problem constants ----------------
#define NB   2
#define NCH  128
#define NH   128
#define NW   128
#define NE   6
#define ND   6
#define NHF  512
#define NHW  (NH*NW)        // 16384
#define NTOK (NB*NH*NW)     // 32768
#define NOUT (NTOK*NCH)
#define GBLK 128            // gate blocks (256 tokens each)
#define LCAP (2*NTOK)       // per-expert list capacity

// ---------------- scratch ----------------
__device__ __align__(16) __half g_xf[NTOK * NCH];        // fp16 activations
__device__ __align__(16) __half g_res[NTOK * 2 * NCH];   // fp16 out+b2 (pre-exp)
__device__ float g_gates[NTOK * 2];                      // fp32 gate per slot
__device__ int   g_list[NE * LCAP];
__device__ float g_gate[NE * LCAP];
__device__ int   g_cnt[NE];
__device__ float g_partW[GBLK * NE];
__device__ float g_partC[GBLK * NE];
__device__ unsigned g_done;

// fp16 weights, B layout [n][k]
__device__ __align__(16) __half g_w1t[NE * NHF * NCH];
__device__ __align__(16) __half g_w2t[NE * NHF * NCH];

// half2 gelu via tanh.approx.f16x2 (2 tanh per MUFU op)
__device__ __forceinline__ unsigned gelu2h(float z0, float z1) {
    float u0 = 0.7978845608028654f * z0 * (1.0f + 0.044715f * z0 * z0);
    float u1 = 0.7978845608028654f * z1 * (1.0f + 0.044715f * z1 * z1);
    __half2 u2 = __floats2half2_rn(u0, u1);
    unsigned t;
    asm("tanh.approx.f16x2 %0, %1;" : "=r"(t) : "r"(*(unsigned*)&u2));
    __half2 zh = __floats2half2_rn(0.5f * z0, 0.5f * z1);
    __half2 h2 = __hfma2(zh, *(__half2*)&t, zh);
    return *(unsigned*)&h2;
}
__device__ __forceinline__ unsigned pack2h(float a0, float a1) {
    __half2 h = __floats2half2_rn(a0, a1);
    return *(unsigned*)&h;
}
__device__ __forceinline__ void mma16816h(float* c, const unsigned* a, const unsigned* b) {
    asm volatile("mma.sync.aligned.m16n8k16.row.col.f32.f16.f16.f32 "
                 "{%0,%1,%2,%3}, {%4,%5,%6,%7}, {%8,%9}, {%0,%1,%2,%3};"
                 : "+f"(c[0]), "+f"(c[1]), "+f"(c[2]), "+f"(c[3])
                 : "r"(a[0]), "r"(a[1]), "r"(a[2]), "r"(a[3]),
                   "r"(b[0]), "r"(b[1]));
}
__device__ __forceinline__ void ldm_x4(unsigned* r, unsigned addr) {
    asm volatile("ldmatrix.sync.aligned.m8n8.x4.shared.b16 {%0,%1,%2,%3}, [%4];"
                 : "=r"(r[0]), "=r"(r[1]), "=r"(r[2]), "=r"(r[3]) : "r"(addr));
}
__device__ __forceinline__ unsigned smem_u32(const void* p) {
    unsigned a;
    asm("{ .reg .u64 t; cvta.to.shared.u64 t, %1; cvt.u32.u64 %0, t; }" : "=r"(a) : "l"(p));
    return a;
}
#define CP16(dst, src) \
    asm volatile("cp.async.cg.shared.global [%0], [%1], 16;" :: "r"(dst), "l"(src))
#define CP_COMMIT() asm volatile("cp.async.commit_group;" ::: "memory")
#define CP_WAIT(n)  asm volatile("cp.async.wait_group %0;" :: "n"(n) : "memory")

// ---------------- kernel 1: zero counters only ----------------
__global__ void k_init() {
    int t = threadIdx.x;
    if (t < NE) g_cnt[t] = 0;
    if (t == 31) g_done = 0;
}

// ---------------- kernel 2: fused gating + transpose + weight prep ----------
#define TPBLK 4096
#define W1ELEM (NE * NHF * NCH)
__global__ void __launch_bounds__(256)
k_pre(const float* __restrict__ x, const float* __restrict__ prompt,
      const float* __restrict__ de_cls, const float* __restrict__ w_g,
      const float* __restrict__ gboost, const float* __restrict__ degra_w,
      const float* __restrict__ degra_b,
      const float* __restrict__ fc1w, const float* __restrict__ fc2w,
      float* __restrict__ out, int out_size) {
    int bid = blockIdx.x;
    int tid = threadIdx.x;

    if (bid < GBLK) {
        // ---------- gating ----------
        __shared__ float wg_s[NCH * NE];
        __shared__ float bias_s[NE];
        __shared__ float wsum[8][NE];
        __shared__ int   wcnt[8][NE];
        __shared__ unsigned is_last_s;
        int warp = tid >> 5, lane = tid & 31;
        int n = bid * 256 + tid;
        int b = n >> 14;

        for (int i = tid; i < NCH * NE; i += 256) wg_s[i] = w_g[i];

        if (warp < NE) {
            int e = warp;
            float s1 = 0.f;
#pragma unroll
            for (int q = 0; q < 4; q++) {
                int c = lane + q * 32;
                s1 += prompt[b * NCH + c] * w_g[(NCH + c) * NE + e];
            }
            float s2 = (lane < ND) ? de_cls[b * ND + lane] * degra_w[lane * NE + e] : 0.f;
            for (int off = 16; off; off >>= 1) {
                s1 += __shfl_down_sync(0xffffffffu, s1, off);
                s2 += __shfl_down_sync(0xffffffffu, s2, off);
            }
            if (lane == 0) bias_s[e] = s1 + gboost[0] * (s2 + degra_b[e]);
        }
        __syncthreads();

        int hw = n & (NHW - 1);
        float acc[NE];
#pragma unroll
        for (int e = 0; e < NE; e++) acc[e] = bias_s[e];
        const float* xb = x + (size_t)b * NCH * NHW + hw;
#pragma unroll 4
        for (int c = 0; c < NCH; c++) {
            float xv = xb[(size_t)c * NHW];
#pragma unroll
            for (int e = 0; e < NE; e++) acc[e] += xv * wg_s[c * NE + e];
        }
        int i0 = 0; float v0 = acc[0];
#pragma unroll
        for (int e = 1; e < NE; e++) if (acc[e] > v0) { v0 = acc[e]; i0 = e; }
        int i1 = (i0 == 0) ? 1 : 0; float v1 = acc[i1];
#pragma unroll
        for (int e = 0; e < NE; e++)
            if (e != i0 && acc[e] > v1) { v1 = acc[e]; i1 = e; }
        float g0 = 1.f / (1.f + expf(v1 - v0));
        float g1 = 1.f - g0;

        int p0 = atomicAdd(&g_cnt[i0], 1);
        g_list[i0 * LCAP + p0] = n * 2 + 0;
        g_gate[i0 * LCAP + p0] = g0;
        int p1 = atomicAdd(&g_cnt[i1], 1);
        g_list[i1 * LCAP + p1] = n * 2 + 1;
        g_gate[i1 * LCAP + p1] = g1;

#pragma unroll
        for (int e = 0; e < NE; e++) {
            float gv = (i0 == e ? g0 : 0.f) + (i1 == e ? g1 : 0.f);
            int   cv = (i0 == e) + (i1 == e);
            for (int off = 16; off; off >>= 1) {
                gv += __shfl_down_sync(0xffffffffu, gv, off);
                cv += __shfl_down_sync(0xffffffffu, cv, off);
            }
            if (lane == 0) { wsum[warp][e] = gv; wcnt[warp][e] = cv; }
        }
        __syncthreads();
        if (tid < NE) {
            float s = 0.f; int c = 0;
#pragma unroll
            for (int w = 0; w < 8; w++) { s += wsum[w][tid]; c += wcnt[w][tid]; }
            g_partW[bid * NE + tid] = s;
            g_partC[bid * NE + tid] = (float)c;
        }
        __threadfence();
        __syncthreads();
        if (tid == 0) is_last_s = (atomicAdd(&g_done, 1u) == GBLK - 1);
        __syncthreads();
        if (is_last_s) {
            if (warp < NE) {
                float sW = g_partW[lane * NE + warp] + g_partW[(lane + 32) * NE + warp]
                         + g_partW[(lane + 64) * NE + warp] + g_partW[(lane + 96) * NE + warp];
                float sC = g_partC[lane * NE + warp] + g_partC[(lane + 32) * NE + warp]
                         + g_partC[(lane + 64) * NE + warp] + g_partC[(lane + 96) * NE + warp];
                for (int off = 16; off; off >>= 1) {
                    sW += __shfl_down_sync(0xffffffffu, sW, off);
                    sC += __shfl_down_sync(0xffffffffu, sC, off);
                }
                if (lane == 0) { wsum[0][warp] = sW; wsum[1][warp] = sC; }
            }
            __syncthreads();
            if (tid == 0 && out_size > NOUT) {
                float mW = 0.f, mC = 0.f;
                for (int e = 0; e < NE; e++) { mW += wsum[0][e]; mC += wsum[1][e]; }
                mW /= NE; mC /= NE;
                float vW = 0.f, vC = 0.f;
                for (int e = 0; e < NE; e++) {
                    vW += (wsum[0][e] - mW) * (wsum[0][e] - mW);
                    vC += (wsum[1][e] - mC) * (wsum[1][e] - mC);
                }
                vW /= (NE - 1); vC /= (NE - 1);
                out[NOUT] = vW / (mW * mW + 1e-10f) + vC / (mC * mC + 1e-10f);
            }
        }
    } else if (bid < GBLK + TPBLK) {
        // ---------- transpose x -> g_xf (fp16) ----------
        __shared__ float tile[32][33];
        int tb = bid - GBLK;
        int cx = tb & 3, wy = (tb >> 2) & 3, bh = tb >> 4;
        int b = bh / NH, h = bh % NH;
        int c0 = cx * 32, w0 = wy * 32;
        int tx = tid & 31, ty = tid >> 5;
        for (int i = ty; i < 32; i += 8)
            tile[i][tx] = x[(((size_t)b * NCH + c0 + i) * NH + h) * NW + w0 + tx];
        __syncthreads();
        for (int i = ty; i < 32; i += 8)
            g_xf[((size_t)(b * NHW + h * NW + w0 + i)) * NCH + c0 + tx] =
                __float2half_rn(tile[tx][i]);
    } else {
        // ---------- weight prep ----------
        int idx = (bid - GBLK - TPBLK) * 256 + tid;
        if (idx < W1ELEM) {
            int e = idx >> 16, rem = idx & 65535;
            int n = rem >> 7, k = rem & 127;
            g_w1t[idx] = __float2half_rn(fc1w[((size_t)e * NCH + k) * NHF + n]);
        } else {
            int j = idx - W1ELEM;
            if (j < W1ELEM) {
                int e = j >> 16, rem = j & 65535;
                int jc = rem >> 13, r2 = rem & 8191;
                int c = r2 >> 6, k = r2 & 63;
                g_w2t[j] = __float2half_rn(fc2w[((size_t)e * NHF + jc * 64 + k) * NCH + c]);
            }
        }
    }
}

// ---------------- kernel 3: fp16 mma MoE, M=256 tiles, 512 threads -----------
// SMEM map (bytes):
#define S2_X     0                     // [256][136] half = 69632
#define S2_W1    69632                 // 2 buffers x [64][136] half = 2*17408
#define S2_W2    104448                // 2 buffers x [128][72] half = 2*18432
#define S2_H     141312                // [256][72] half = 36864
#define S2_SLOT  178176                // 256 int
#define S2_GATE  179200                // 256 float
#define S2_BYTES 180224

__global__ void __launch_bounds__(512, 1)
k_moe(const float* __restrict__ fc1b, const float* __restrict__ fc2b) {
    int e    = blockIdx.x >> 8;
    int tile = blockIdx.x & 255;
    int cnt  = g_cnt[e];
    int row0 = tile << 8;
    if (row0 >= cnt) return;

    extern __shared__ char sm[];
    unsigned sb = smem_u32(sm);
    __half* Hs = (__half*)(sm + S2_H);
    int*   slot_s = (int*)(sm + S2_SLOT);
    float* gate_s = (float*)(sm + S2_GATE);

    int tid = threadIdx.x;
    int wid = tid >> 5, lt = tid & 31;
    int qr = lt >> 2, qc = lt & 3;
    int mb  = (wid & 7) * 32;          // warp m-block (32 of 256 rows)
    int nb1 = (wid >> 3) * 32;         // GEMM1 n-block
    int nb2 = (wid >> 3) * 64;         // GEMM2 n-block
    int lrow = lt & 15;
    int lcol = (lt & 16) >> 1;

    const __half* w1g = g_w1t + (size_t)e * NHF * NCH;
    const __half* w2g = g_w2t + (size_t)e * NHF * NCH;

    // prologue: W1(0)+W2(0) into buffer 0 as one group
    {
        unsigned d1 = sb + S2_W1, d2 = sb + S2_W2;
#pragma unroll
        for (int it = 0; it < 2; it++) {
            int u = tid + it * 512;              // 0..1023
            int n1 = u >> 4, k16 = u & 15;
            CP16(d1 + (unsigned)(n1 * 136 + k16 * 8) * 2, w1g + n1 * NCH + k16 * 8);
            int n2 = u >> 3, k8 = u & 7;
            CP16(d2 + (unsigned)(n2 * 72 + k8 * 8) * 2, w2g + n2 * 64 + k8 * 8);
        }
        CP_COMMIT();
    }

    if (tid < 256) {
        int r = row0 + tid;
        if (r < cnt) {
            int s = g_list[e * LCAP + r];
            float g = g_gate[e * LCAP + r];
            slot_s[tid] = s; gate_s[tid] = g;
            g_gates[s] = g;                       // per-slot gate for k_out
        } else { slot_s[tid] = -1; gate_s[tid] = 0.f; }
    }
    __syncthreads();

    // gather X (fp16) -> smem, straight uint4 copies: 256 rows x 16 chunks
#pragma unroll
    for (int it = 0; it < 8; it++) {
        int idx = tid + it * 512;           // 0..4095
        int r = idx >> 4, c8 = idx & 15;
        uint4 U = make_uint4(0u, 0u, 0u, 0u);
        int s = slot_s[r];
        if (s >= 0)
            U = *(const uint4*)(g_xf + (size_t)(s >> 1) * NCH + c8 * 8);
        *(uint4*)((__half*)(sm + S2_X) + r * 136 + c8 * 8) = U;
    }

    float acc2[2][8][4];
#pragma unroll
    for (int i = 0; i < 2; i++)
#pragma unroll
        for (int j = 0; j < 8; j++)
#pragma unroll
            for (int q = 0; q < 4; q++) acc2[i][j][q] = 0.f;

    unsigned aX  = sb + S2_X  + (unsigned)((mb + lrow) * 136 + lcol) * 2;
    unsigned aH  = sb + S2_H  + (unsigned)((mb + lrow) * 72  + lcol) * 2;

    for (int jc = 0; jc < 8; jc++) {
        int cur = jc & 1;
        CP_WAIT(0);              // W1(jc)+W2(jc) arrived (issued last chunk)
        __syncthreads();         // all warps done with prev buffers + H reads

        // prefetch W1(jc+1)+W2(jc+1) into other buffers (one group)
        if (jc < 7) {
            unsigned d1 = sb + S2_W1 + (1 - cur) * 17408;
            unsigned d2 = sb + S2_W2 + (1 - cur) * 18432;
            const __half* s1 = w1g + (jc + 1) * 64 * NCH;
            const __half* s2 = w2g + (jc + 1) * 8192;
#pragma unroll
            for (int it = 0; it < 2; it++) {
                int u = tid + it * 512;
                int n1 = u >> 4, k16 = u & 15;
                CP16(d1 + (unsigned)(n1 * 136 + k16 * 8) * 2, s1 + n1 * NCH + k16 * 8);
                int n2 = u >> 3, k8 = u & 7;
                CP16(d2 + (unsigned)(n2 * 72 + k8 * 8) * 2, s2 + n2 * 64 + k8 * 8);
            }
            CP_COMMIT();
        }

        unsigned bW1 = sb + S2_W1 + cur * 17408 + (unsigned)((nb1 + lrow) * 136 + lcol) * 2;
        unsigned bW2 = sb + S2_W2 + cur * 18432 + (unsigned)((nb2 + lrow) * 72 + lcol) * 2;

        // GEMM1: warp tile m32 x n32
        float acc1[2][4][4];
#pragma unroll
        for (int i = 0; i < 2; i++)
#pragma unroll
            for (int j = 0; j < 4; j++)
#pragma unroll
                for (int q = 0; q < 4; q++) acc1[i][j][q] = 0.f;

#pragma unroll
        for (int kt = 0; kt < 8; kt++) {
            unsigned a0[4], a1[4];
            ldm_x4(a0, aX + kt * 32);
            ldm_x4(a1, aX + 16 * 136 * 2 + kt * 32);
#pragma unroll
            for (int j2 = 0; j2 < 2; j2++) {
                unsigned r[4];
                ldm_x4(r, bW1 + (unsigned)(j2 * 16 * 136) * 2 + kt * 32);
                unsigned b0[2] = { r[0], r[2] };
                unsigned b1[2] = { r[1], r[3] };
                mma16816h(acc1[0][2 * j2],     a0, b0);
                mma16816h(acc1[0][2 * j2 + 1], a0, b1);
                mma16816h(acc1[1][2 * j2],     a1, b0);
                mma16816h(acc1[1][2 * j2 + 1], a1, b1);
            }
        }
        // bias + half2 gelu -> H
#pragma unroll
        for (int i = 0; i < 2; i++)
#pragma unroll
            for (int j = 0; j < 4; j++) {
                int n = nb1 + j * 8 + qc * 2;
                float2 b1v = *(const float2*)(fc1b + e * NHF + jc * 64 + n);
                *(unsigned*)(Hs + (mb + i * 16 + qr) * 72 + n) =
                    gelu2h(acc1[i][j][0] + b1v.x, acc1[i][j][1] + b1v.y);
                *(unsigned*)(Hs + (mb + i * 16 + qr + 8) * 72 + n) =
                    gelu2h(acc1[i][j][2] + b1v.x, acc1[i][j][3] + b1v.y);
            }
        __syncthreads();         // H visible to all warps

        // GEMM2: warp tile m32 x n64
#pragma unroll
        for (int kt = 0; kt < 4; kt++) {
            unsigned a0[4], a1[4];
            ldm_x4(a0, aH + kt * 32);
            ldm_x4(a1, aH + 16 * 72 * 2 + kt * 32);
#pragma unroll
            for (int j2 = 0; j2 < 4; j2++) {
                unsigned r[4];
                ldm_x4(r, bW2 + (unsigned)(j2 * 16 * 72) * 2 + kt * 32);
                unsigned b0[2] = { r[0], r[2] };
                unsigned b1[2] = { r[1], r[3] };
                mma16816h(acc2[0][2 * j2],     a0, b0);
                mma16816h(acc2[0][2 * j2 + 1], a0, b1);
                mma16816h(acc2[1][2 * j2],     a1, b0);
                mma16816h(acc2[1][2 * j2 + 1], a1, b1);
            }
        }
        // no loop-end sync: next chunk's top sync orders H/W overwrites
    }

    // epilogue: store PRE-EXP logits (out + b2) as fp16
#pragma unroll
    for (int i = 0; i < 2; i++) {
        int mAr = mb + i * 16 + qr, mBr = mAr + 8;
        int sA = slot_s[mAr], sB = slot_s[mBr];
#pragma unroll
        for (int j = 0; j < 8; j++) {
            int c = nb2 + j * 8 + qc * 2;
            float2 b2 = *(const float2*)(fc2b + e * NCH + c);
            if (sA >= 0) {
                *(unsigned*)(g_res + (size_t)sA * NCH + c) =
                    pack2h(acc2[0][j][0] + b2.x, acc2[0][j][1] + b2.y);
            }
            if (sB >= 0) {
                *(unsigned*)(g_res + (size_t)sB * NCH + c) =
                    pack2h(acc2[0][j][2] + b2.x, acc2[0][j][3] + b2.y);
            }
            // second m16 tile
            if (i == 1) break;
        }
        if (i == 0) {
            // handled tile 0 above with acc2[0]; tile 1 below
        }
    }
    // (explicit second-tile epilogue to keep acc indexing clear)
#pragma unroll
    for (int j = 0; j < 8; j++) {
        int mAr = mb + 16 + qr, mBr = mAr + 8;
        int sA = slot_s[mAr], sB = slot_s[mBr];
        int c = nb2 + j * 8 + qc * 2;
        float2 b2 = *(const float2*)(fc2b + e * NCH + c);
        if (sA >= 0) {
            *(unsigned*)(g_res + (size_t)sA * NCH + c) =
                pack2h(acc2[1][j][0] + b2.x, acc2[1][j][1] + b2.y);
        }
        if (sB >= 0) {
            *(unsigned*)(g_res + (size_t)sB * NCH + c) =
                pack2h(acc2[1][j][2] + b2.x, acc2[1][j][3] + b2.y);
        }
    }
}

// ---------------- kernel 4: combine: log(g0 e^o0 + g1 e^o1) + transpose ------
__global__ void __launch_bounds__(256)
k_out(float* __restrict__ out) {
    __shared__ float tile[64][33];
    int bh = blockIdx.z;
    int b = bh / NH, h = bh % NH;
    int c0 = blockIdx.x * 64, w0 = blockIdx.y * 32;
    int tx = threadIdx.x & 31, ty = threadIdx.x >> 5;
    for (int i = ty; i < 32; i += 8) {
        int token = b * NHW + h * NW + w0 + i;
        float g0 = g_gates[token * 2];
        float g1 = g_gates[token * 2 + 1];
        size_t base = (size_t)token * 2 * NCH;
        __half2 o0 = *(const __half2*)(g_res + base + c0 + 2 * tx);
        __half2 o1 = *(const __half2*)(g_res + base + NCH + c0 + 2 * tx);
        float v0 = g0 * __expf(__low2float(o0))  + g1 * __expf(__low2float(o1));
        float v1 = g0 * __expf(__high2float(o0)) + g1 * __expf(__high2float(o1));
        if (v0 == 0.f) v0 = 2.2204460492503131e-16f;
        if (v1 == 0.f) v1 = 2.2204460492503131e-16f;
        tile[2 * tx][i]     = __logf(v0);
        tile[2 * tx + 1][i] = __logf(v1);
    }
    __syncthreads();
    for (int j = ty; j < 64; j += 8)
        out[((size_t)(b * NCH + c0 + j)) * NHW + h * NW + w0 + tx] = tile[j][tx];
}

// ---------------- launch ----------------
extern "C" void kernel_launch(void* const* d_in, const int* in_sizes, int n_in,
                              void* d_out, int out_size) {
    (void)in_sizes; (void)n_in;
    const float* x       = (const float*)d_in[0];
    const float* prompt  = (const float*)d_in[1];
    const float* de_cls  = (const float*)d_in[2];
    const float* w_g     = (const float*)d_in[3];
    const float* gboost  = (const float*)d_in[4];
    const float* degra_w = (const float*)d_in[5];
    const float* degra_b = (const float*)d_in[6];
    const float* fc1w    = (const float*)d_in[7];
    const float* fc1b    = (const float*)d_in[8];
    const float* fc2w    = (const float*)d_in[9];
    const float* fc2b    = (const float*)d_in[10];
    float* out = (float*)d_out;

    k_init<<<1, 32>>>();
    k_pre<<<GBLK + TPBLK + 3072, 256>>>(x, prompt, de_cls, w_g, gboost,
                                        degra_w, degra_b, fc1w, fc2w,
                                        out, out_size);

    cudaFuncSetAttribute(k_moe, cudaFuncAttributeMaxDynamicSharedMemorySize, S2_BYTES);
    k_moe<<<NE * 256, 512, S2_BYTES>>>(fc1b, fc2b);

    k_out<<<dim3(NCH / 64, NW / 32, NB * NH), 256>>>(out);
}

// round 17
// speedup vs baseline: 1.4301x; 1.0058x over previous
#include <cuda_runtime.h>
#include <cuda_bf16.h>
#include <cuda_fp16.h>
#include <math.h>

// ---------------- problem constants ----------------
#define NB   2
#define NCH  128
#define NH   128
#define NW   128
#define NE   6
#define ND   6
#define NHF  512
#define NHW  (NH*NW)        // 16384
#define NTOK (NB*NH*NW)     // 32768
#define NOUT (NTOK*NCH)
#define GBLK 128            // gate blocks (256 tokens each)
#define LCAP (2*NTOK)       // per-expert list capacity

// ---------------- scratch ----------------
__device__ __align__(16) __half g_xf[NTOK * NCH];        // fp16 activations
__device__ __align__(16) __half g_res[NTOK * 2 * NCH];   // fp16 out+b2 (pre-exp)
__device__ float g_gates[NTOK * 2];                      // fp32 gate per slot
__device__ int   g_list[NE * LCAP];
__device__ float g_gate[NE * LCAP];
__device__ int   g_ctr[NE + 1];                          // [0..NE) counts, [NE] done
__device__ float g_partW[GBLK * NE];
__device__ float g_partC[GBLK * NE];

// fp16 weights, B layout [n][k]
__device__ __align__(16) __half g_w1t[NE * NHF * NCH];
__device__ __align__(16) __half g_w2t[NE * NHF * NCH];

// fully-half2 gelu: u and tanh both f16x2 (1 MUFU per 2 elems)
__device__ __forceinline__ unsigned gelu2h(float z0, float z1) {
    __half2 z  = __floats2half2_rn(z0, z1);
    __half2 z2 = __hmul2(z, z);
    __half2 inner = __hfma2(__float2half2_rn(0.044715f), z2,
                            __float2half2_rn(1.0f));
    __half2 u = __hmul2(__hmul2(__float2half2_rn(0.7978845608028654f), z), inner);
    unsigned t;
    asm("tanh.approx.f16x2 %0, %1;" : "=r"(t) : "r"(*(unsigned*)&u));
    __half2 zh = __hmul2(__float2half2_rn(0.5f), z);
    __half2 h2 = __hfma2(zh, *(__half2*)&t, zh);
    return *(unsigned*)&h2;
}
__device__ __forceinline__ unsigned pack2h(float a0, float a1) {
    __half2 h = __floats2half2_rn(a0, a1);
    return *(unsigned*)&h;
}
__device__ __forceinline__ void mma16816h(float* c, const unsigned* a, const unsigned* b) {
    asm volatile("mma.sync.aligned.m16n8k16.row.col.f32.f16.f16.f32 "
                 "{%0,%1,%2,%3}, {%4,%5,%6,%7}, {%8,%9}, {%0,%1,%2,%3};"
                 : "+f"(c[0]), "+f"(c[1]), "+f"(c[2]), "+f"(c[3])
                 : "r"(a[0]), "r"(a[1]), "r"(a[2]), "r"(a[3]),
                   "r"(b[0]), "r"(b[1]));
}
__device__ __forceinline__ void ldm_x4(unsigned* r, unsigned addr) {
    asm volatile("ldmatrix.sync.aligned.m8n8.x4.shared.b16 {%0,%1,%2,%3}, [%4];"
                 : "=r"(r[0]), "=r"(r[1]), "=r"(r[2]), "=r"(r[3]) : "r"(addr));
}
__device__ __forceinline__ unsigned smem_u32(const void* p) {
    unsigned a;
    asm("{ .reg .u64 t; cvta.to.shared.u64 t, %1; cvt.u32.u64 %0, t; }" : "=r"(a) : "l"(p));
    return a;
}
#define CP16(dst, src) \
    asm volatile("cp.async.cg.shared.global [%0], [%1], 16;" :: "r"(dst), "l"(src))
#define CP_COMMIT() asm volatile("cp.async.commit_group;" ::: "memory")
#define CP_WAIT(n)  asm volatile("cp.async.wait_group %0;" :: "n"(n) : "memory")

// ---------------- kernel 1: fused gating + transpose + weight prep ----------
#define TPBLK 2048          // 64c x 32w transpose tiles
#define W1ELEM (NE * NHF * NCH)
__global__ void __launch_bounds__(256)
k_pre(const float* __restrict__ x, const float* __restrict__ prompt,
      const float* __restrict__ de_cls, const float* __restrict__ w_g,
      const float* __restrict__ gboost, const float* __restrict__ degra_w,
      const float* __restrict__ degra_b,
      const float* __restrict__ fc1w, const float* __restrict__ fc2w,
      float* __restrict__ out, int out_size) {
    int bid = blockIdx.x;
    int tid = threadIdx.x;

    if (bid < GBLK) {
        // ---------- gating ----------
        __shared__ float wg_s[NCH * NE];
        __shared__ float bias_s[NE];
        __shared__ float wsum[8][NE];
        __shared__ int   wcnt[8][NE];
        __shared__ unsigned is_last_s;
        int warp = tid >> 5, lane = tid & 31;
        int n = bid * 256 + tid;
        int b = n >> 14;

        for (int i = tid; i < NCH * NE; i += 256) wg_s[i] = w_g[i];

        if (warp < NE) {
            int e = warp;
            float s1 = 0.f;
#pragma unroll
            for (int q = 0; q < 4; q++) {
                int c = lane + q * 32;
                s1 += prompt[b * NCH + c] * w_g[(NCH + c) * NE + e];
            }
            float s2 = (lane < ND) ? de_cls[b * ND + lane] * degra_w[lane * NE + e] : 0.f;
            for (int off = 16; off; off >>= 1) {
                s1 += __shfl_down_sync(0xffffffffu, s1, off);
                s2 += __shfl_down_sync(0xffffffffu, s2, off);
            }
            if (lane == 0) bias_s[e] = s1 + gboost[0] * (s2 + degra_b[e]);
        }
        __syncthreads();

        int hw = n & (NHW - 1);
        float acc[NE];
#pragma unroll
        for (int e = 0; e < NE; e++) acc[e] = bias_s[e];
        const float* xb = x + (size_t)b * NCH * NHW + hw;
#pragma unroll 4
        for (int c = 0; c < NCH; c++) {
            float xv = xb[(size_t)c * NHW];
#pragma unroll
            for (int e = 0; e < NE; e++) acc[e] += xv * wg_s[c * NE + e];
        }
        int i0 = 0; float v0 = acc[0];
#pragma unroll
        for (int e = 1; e < NE; e++) if (acc[e] > v0) { v0 = acc[e]; i0 = e; }
        int i1 = (i0 == 0) ? 1 : 0; float v1 = acc[i1];
#pragma unroll
        for (int e = 0; e < NE; e++)
            if (e != i0 && acc[e] > v1) { v1 = acc[e]; i1 = e; }
        float g0 = 1.f / (1.f + expf(v1 - v0));
        float g1 = 1.f - g0;

        int p0 = atomicAdd(&g_ctr[i0], 1);
        g_list[i0 * LCAP + p0] = n * 2 + 0;
        g_gate[i0 * LCAP + p0] = g0;
        int p1 = atomicAdd(&g_ctr[i1], 1);
        g_list[i1 * LCAP + p1] = n * 2 + 1;
        g_gate[i1 * LCAP + p1] = g1;

#pragma unroll
        for (int e = 0; e < NE; e++) {
            float gv = (i0 == e ? g0 : 0.f) + (i1 == e ? g1 : 0.f);
            int   cv = (i0 == e) + (i1 == e);
            for (int off = 16; off; off >>= 1) {
                gv += __shfl_down_sync(0xffffffffu, gv, off);
                cv += __shfl_down_sync(0xffffffffu, cv, off);
            }
            if (lane == 0) { wsum[warp][e] = gv; wcnt[warp][e] = cv; }
        }
        __syncthreads();
        if (tid < NE) {
            float s = 0.f; int c = 0;
#pragma unroll
            for (int w = 0; w < 8; w++) { s += wsum[w][tid]; c += wcnt[w][tid]; }
            g_partW[bid * NE + tid] = s;
            g_partC[bid * NE + tid] = (float)c;
        }
        __threadfence();
        __syncthreads();
        if (tid == 0) is_last_s = (atomicAdd(&g_ctr[NE], 1) == GBLK - 1);
        __syncthreads();
        if (is_last_s) {
            if (warp < NE) {
                float sW = g_partW[lane * NE + warp] + g_partW[(lane + 32) * NE + warp]
                         + g_partW[(lane + 64) * NE + warp] + g_partW[(lane + 96) * NE + warp];
                float sC = g_partC[lane * NE + warp] + g_partC[(lane + 32) * NE + warp]
                         + g_partC[(lane + 64) * NE + warp] + g_partC[(lane + 96) * NE + warp];
                for (int off = 16; off; off >>= 1) {
                    sW += __shfl_down_sync(0xffffffffu, sW, off);
                    sC += __shfl_down_sync(0xffffffffu, sC, off);
                }
                if (lane == 0) { wsum[0][warp] = sW; wsum[1][warp] = sC; }
            }
            __syncthreads();
            if (tid == 0 && out_size > NOUT) {
                float mW = 0.f, mC = 0.f;
                for (int e = 0; e < NE; e++) { mW += wsum[0][e]; mC += wsum[1][e]; }
                mW /= NE; mC /= NE;
                float vW = 0.f, vC = 0.f;
                for (int e = 0; e < NE; e++) {
                    vW += (wsum[0][e] - mW) * (wsum[0][e] - mW);
                    vC += (wsum[1][e] - mC) * (wsum[1][e] - mC);
                }
                vW /= (NE - 1); vC /= (NE - 1);
                out[NOUT] = vW / (mW * mW + 1e-10f) + vC / (mC * mC + 1e-10f);
            }
        }
    } else if (bid < GBLK + TPBLK) {
        // ---------- transpose x -> g_xf (fp16), 64c x 32w tiles --------------
        __shared__ float tile[64][33];
        int tb = bid - GBLK;
        int cx = tb & 1, wy = (tb >> 1) & 3, bh = tb >> 3;
        int b = bh / NH, h = bh % NH;
        int c0 = cx * 64, w0 = wy * 32;
        int tx = tid & 31, ty = tid >> 5;
        for (int ci = ty; ci < 64; ci += 8)
            tile[ci][tx] = x[(((size_t)b * NCH + c0 + ci) * NH + h) * NW + w0 + tx];
        __syncthreads();
        // write: each thread emits one half2 (2 consecutive c) -> 128B/token
#pragma unroll
        for (int p = 0; p < 4; p++) {
            int u = tid + p * 256;          // 0..1023
            int i = u >> 5, c2 = u & 31;    // token row, half2 index
            __half2 v = __floats2half2_rn(tile[2 * c2][i], tile[2 * c2 + 1][i]);
            *(__half2*)(g_xf + ((size_t)(b * NHW + h * NW + w0 + i)) * NCH
                        + c0 + 2 * c2) = v;
        }
    } else {
        // ---------- weight prep ----------
        int idx = (bid - GBLK - TPBLK) * 256 + tid;
        if (idx < W1ELEM) {
            int e = idx >> 16, rem = idx & 65535;
            int n = rem >> 7, k = rem & 127;
            g_w1t[idx] = __float2half_rn(fc1w[((size_t)e * NCH + k) * NHF + n]);
        } else {
            int j = idx - W1ELEM;
            if (j < W1ELEM) {
                int e = j >> 16, rem = j & 65535;
                int jc = rem >> 13, r2 = rem & 8191;
                int c = r2 >> 6, k = r2 & 63;
                g_w2t[j] = __float2half_rn(fc2w[((size_t)e * NHF + jc * 64 + k) * NCH + c]);
            }
        }
    }
}

// ---------------- kernel 2: fp16 mma MoE, M=256 tiles, 512 threads -----------
// SMEM map (bytes):
#define S2_X     0                     // [256][136] half = 69632
#define S2_W1    69632                 // 2 buffers x [64][136] half = 2*17408
#define S2_W2    104448                // 2 buffers x [128][72] half = 2*18432
#define S2_H     141312                // [256][72] half = 36864
#define S2_SLOT  178176                // 256 int
#define S2_GATE  179200                // 256 float
#define S2_BYTES 180224

__global__ void __launch_bounds__(512, 1)
k_moe(const float* __restrict__ fc1b, const float* __restrict__ fc2b) {
    int e    = blockIdx.x >> 8;
    int tile = blockIdx.x & 255;
    int cnt  = g_ctr[e];
    int row0 = tile << 8;
    if (row0 >= cnt) return;

    extern __shared__ char sm[];
    unsigned sb = smem_u32(sm);
    __half* Hs = (__half*)(sm + S2_H);
    int*   slot_s = (int*)(sm + S2_SLOT);
    float* gate_s = (float*)(sm + S2_GATE);

    int tid = threadIdx.x;
    int wid = tid >> 5, lt = tid & 31;
    int qr = lt >> 2, qc = lt & 3;
    int mb  = (wid & 7) * 32;
    int nb1 = (wid >> 3) * 32;
    int nb2 = (wid >> 3) * 64;
    int lrow = lt & 15;
    int lcol = (lt & 16) >> 1;

    const __half* w1g = g_w1t + (size_t)e * NHF * NCH;
    const __half* w2g = g_w2t + (size_t)e * NHF * NCH;

    // prologue: W1(0)+W2(0) into buffer 0 as one group
    {
        unsigned d1 = sb + S2_W1, d2 = sb + S2_W2;
#pragma unroll
        for (int it = 0; it < 2; it++) {
            int u = tid + it * 512;
            int n1 = u >> 4, k16 = u & 15;
            CP16(d1 + (unsigned)(n1 * 136 + k16 * 8) * 2, w1g + n1 * NCH + k16 * 8);
            int n2 = u >> 3, k8 = u & 7;
            CP16(d2 + (unsigned)(n2 * 72 + k8 * 8) * 2, w2g + n2 * 64 + k8 * 8);
        }
        CP_COMMIT();
    }

    if (tid < 256) {
        int r = row0 + tid;
        if (r < cnt) {
            int s = g_list[e * LCAP + r];
            float g = g_gate[e * LCAP + r];
            slot_s[tid] = s; gate_s[tid] = g;
            g_gates[s] = g;
        } else { slot_s[tid] = -1; gate_s[tid] = 0.f; }
    }
    __syncthreads();

    // gather X (fp16) -> smem
#pragma unroll
    for (int it = 0; it < 8; it++) {
        int idx = tid + it * 512;
        int r = idx >> 4, c8 = idx & 15;
        uint4 U = make_uint4(0u, 0u, 0u, 0u);
        int s = slot_s[r];
        if (s >= 0)
            U = *(const uint4*)(g_xf + (size_t)(s >> 1) * NCH + c8 * 8);
        *(uint4*)((__half*)(sm + S2_X) + r * 136 + c8 * 8) = U;
    }

    float acc2[2][8][4];
#pragma unroll
    for (int i = 0; i < 2; i++)
#pragma unroll
        for (int j = 0; j < 8; j++)
#pragma unroll
            for (int q = 0; q < 4; q++) acc2[i][j][q] = 0.f;

    unsigned aX = sb + S2_X + (unsigned)((mb + lrow) * 136 + lcol) * 2;
    unsigned aH = sb + S2_H + (unsigned)((mb + lrow) * 72  + lcol) * 2;

    for (int jc = 0; jc < 8; jc++) {
        int cur = jc & 1;
        CP_WAIT(0);
        __syncthreads();

        if (jc < 7) {
            unsigned d1 = sb + S2_W1 + (1 - cur) * 17408;
            unsigned d2 = sb + S2_W2 + (1 - cur) * 18432;
            const __half* s1 = w1g + (jc + 1) * 64 * NCH;
            const __half* s2 = w2g + (jc + 1) * 8192;
#pragma unroll
            for (int it = 0; it < 2; it++) {
                int u = tid + it * 512;
                int n1 = u >> 4, k16 = u & 15;
                CP16(d1 + (unsigned)(n1 * 136 + k16 * 8) * 2, s1 + n1 * NCH + k16 * 8);
                int n2 = u >> 3, k8 = u & 7;
                CP16(d2 + (unsigned)(n2 * 72 + k8 * 8) * 2, s2 + n2 * 64 + k8 * 8);
            }
            CP_COMMIT();
        }

        unsigned bW1 = sb + S2_W1 + cur * 17408 + (unsigned)((nb1 + lrow) * 136 + lcol) * 2;
        unsigned bW2 = sb + S2_W2 + cur * 18432 + (unsigned)((nb2 + lrow) * 72 + lcol) * 2;

        // GEMM1: warp tile m32 x n32
        float acc1[2][4][4];
#pragma unroll
        for (int i = 0; i < 2; i++)
#pragma unroll
            for (int j = 0; j < 4; j++)
#pragma unroll
                for (int q = 0; q < 4; q++) acc1[i][j][q] = 0.f;

#pragma unroll
        for (int kt = 0; kt < 8; kt++) {
            unsigned a0[4], a1[4];
            ldm_x4(a0, aX + kt * 32);
            ldm_x4(a1, aX + 16 * 136 * 2 + kt * 32);
#pragma unroll
            for (int j2 = 0; j2 < 2; j2++) {
                unsigned r[4];
                ldm_x4(r, bW1 + (unsigned)(j2 * 16 * 136) * 2 + kt * 32);
                unsigned b0[2] = { r[0], r[2] };
                unsigned b1[2] = { r[1], r[3] };
                mma16816h(acc1[0][2 * j2],     a0, b0);
                mma16816h(acc1[0][2 * j2 + 1], a0, b1);
                mma16816h(acc1[1][2 * j2],     a1, b0);
                mma16816h(acc1[1][2 * j2 + 1], a1, b1);
            }
        }
        // bias + half2 gelu -> H
#pragma unroll
        for (int i = 0; i < 2; i++)
#pragma unroll
            for (int j = 0; j < 4; j++) {
                int n = nb1 + j * 8 + qc * 2;
                float2 b1v = *(const float2*)(fc1b + e * NHF + jc * 64 + n);
                *(unsigned*)(Hs + (mb + i * 16 + qr) * 72 + n) =
                    gelu2h(acc1[i][j][0] + b1v.x, acc1[i][j][1] + b1v.y);
                *(unsigned*)(Hs + (mb + i * 16 + qr + 8) * 72 + n) =
                    gelu2h(acc1[i][j][2] + b1v.x, acc1[i][j][3] + b1v.y);
            }
        __syncthreads();

        // GEMM2: warp tile m32 x n64
#pragma unroll
        for (int kt = 0; kt < 4; kt++) {
            unsigned a0[4], a1[4];
            ldm_x4(a0, aH + kt * 32);
            ldm_x4(a1, aH + 16 * 72 * 2 + kt * 32);
#pragma unroll
            for (int j2 = 0; j2 < 4; j2++) {
                unsigned r[4];
                ldm_x4(r, bW2 + (unsigned)(j2 * 16 * 72) * 2 + kt * 32);
                unsigned b0[2] = { r[0], r[2] };
                unsigned b1[2] = { r[1], r[3] };
                mma16816h(acc2[0][2 * j2],     a0, b0);
                mma16816h(acc2[0][2 * j2 + 1], a0, b1);
                mma16816h(acc2[1][2 * j2],     a1, b0);
                mma16816h(acc2[1][2 * j2 + 1], a1, b1);
            }
        }
    }

    // epilogue: store PRE-EXP logits (out + b2) as fp16
#pragma unroll
    for (int i = 0; i < 2; i++) {
        int mAr = mb + i * 16 + qr, mBr = mAr + 8;
        int sA = slot_s[mAr], sB = slot_s[mBr];
#pragma unroll
        for (int j = 0; j < 8; j++) {
            int c = nb2 + j * 8 + qc * 2;
            float2 b2 = *(const float2*)(fc2b + e * NCH + c);
            if (sA >= 0) {
                *(unsigned*)(g_res + (size_t)sA * NCH + c) =
                    pack2h(acc2[i][j][0] + b2.x, acc2[i][j][1] + b2.y);
            }
            if (sB >= 0) {
                *(unsigned*)(g_res + (size_t)sB * NCH + c) =
                    pack2h(acc2[i][j][2] + b2.x, acc2[i][j][3] + b2.y);
            }
        }
    }
}

// ---------------- kernel 3: combine: log(g0 e^o0 + g1 e^o1) + transpose ------
__global__ void __launch_bounds__(256)
k_out(float* __restrict__ out) {
    __shared__ float tile[64][33];
    int bh = blockIdx.z;
    int b = bh / NH, h = bh % NH;
    int c0 = blockIdx.x * 64, w0 = blockIdx.y * 32;
    int tx = threadIdx.x & 31, ty = threadIdx.x >> 5;
    for (int i = ty; i < 32; i += 8) {
        int token = b * NHW + h * NW + w0 + i;
        float g0 = g_gates[token * 2];
        float g1 = g_gates[token * 2 + 1];
        size_t base = (size_t)token * 2 * NCH;
        __half2 o0 = *(const __half2*)(g_res + base + c0 + 2 * tx);
        __half2 o1 = *(const __half2*)(g_res + base + NCH + c0 + 2 * tx);
        float v0 = g0 * __expf(__low2float(o0))  + g1 * __expf(__low2float(o1));
        float v1 = g0 * __expf(__high2float(o0)) + g1 * __expf(__high2float(o1));
        if (v0 == 0.f) v0 = 2.2204460492503131e-16f;
        if (v1 == 0.f) v1 = 2.2204460492503131e-16f;
        tile[2 * tx][i]     = __logf(v0);
        tile[2 * tx + 1][i] = __logf(v1);
    }
    __syncthreads();
    for (int j = ty; j < 64; j += 8)
        out[((size_t)(b * NCH + c0 + j)) * NHW + h * NW + w0 + tx] = tile[j][tx];
}

// ---------------- launch ----------------
extern "C" void kernel_launch(void* const* d_in, const int* in_sizes, int n_in,
                              void* d_out, int out_size) {
    (void)in_sizes; (void)n_in;
    const float* x       = (const float*)d_in[0];
    const float* prompt  = (const float*)d_in[1];
    const float* de_cls  = (const float*)d_in[2];
    const float* w_g     = (const float*)d_in[3];
    const float* gboost  = (const float*)d_in[4];
    const float* degra_w = (const float*)d_in[5];
    const float* degra_b = (const float*)d_in[6];
    const float* fc1w    = (const float*)d_in[7];
    const float* fc1b    = (const float*)d_in[8];
    const float* fc2w    = (const float*)d_in[9];
    const float* fc2b    = (const float*)d_in[10];
    float* out = (float*)d_out;

    static void* ctr_ptr = nullptr;
    static int cfg_done = 0;
    if (!cfg_done) {
        cudaGetSymbolAddress(&ctr_ptr, g_ctr);
        cudaFuncSetAttribute(k_moe, cudaFuncAttributeMaxDynamicSharedMemorySize,
                             S2_BYTES);
        cfg_done = 1;
    }
    cudaMemsetAsync(ctr_ptr, 0, sizeof(int) * (NE + 1));

    k_pre<<<GBLK + TPBLK + 3072, 256>>>(x, prompt, de_cls, w_g, gboost,
                                        degra_w, degra_b, fc1w, fc2w,
                                        out, out_size);
    k_moe<<<NE * 256, 512, S2_BYTES>>>(fc1b, fc2b);
    k_out<<<dim3(NCH / 64, NW / 32, NB * NH), 256>>>(out);
}